// round 8
// baseline (speedup 1.0000x reference)
#include <cuda_runtime.h>
#include <cuda_bf16.h>
#include <stdint.h>
#include <math.h>

#define BB   64
#define LL   384
#define DDIM 128
#define HH   8
#define DHH  16
#define NDEPTH 6
#define FFD  512
#define BLD  (BB*LL)          /* 24576 rows */
#define KP   (LL*DDIM)        /* 49152     */
#define NSPLIT 32
#define KSPLIT (KP/NSPLIT)    /* 1536 */

/* ------------------------------------------------------------------ scratch */
__device__ float g_x1[BLD*DDIM];
__device__ float g_x2[BLD*DDIM];
__device__ float g_h [BLD*DDIM];          /* fp32 (final LN -> proj) */
__device__ float g_qkv[BLD*2*DDIM];       /* fused qk|v output [row][256] */
__device__ float g_part[NSPLIT*BB*128];

__device__ __nv_bfloat16 g_hh[BLD*DDIM];  /* LN output split */
__device__ __nv_bfloat16 g_hl[BLD*DDIM];
__device__ __nv_bfloat16 g_oh[BLD*DDIM];  /* attention output split */
__device__ __nv_bfloat16 g_ol[BLD*DDIM];
__device__ __nv_bfloat16 g_ah[BLD*FFD];   /* FF1 output split */
__device__ __nv_bfloat16 g_al[BLD*FFD];

/* transposed + split weights: [layer][N][K] */
__device__ __nv_bfloat16 g_wqvh[NDEPTH*2*DDIM*DDIM], g_wqvl[NDEPTH*2*DDIM*DDIM];
__device__ __nv_bfloat16 g_woh [NDEPTH*DDIM*DDIM],   g_wol [NDEPTH*DDIM*DDIM];
__device__ __nv_bfloat16 g_w1h [NDEPTH*DDIM*FFD],    g_w1l [NDEPTH*DDIM*FFD];
__device__ __nv_bfloat16 g_w2h [NDEPTH*FFD*DDIM],    g_w2l [NDEPTH*FFD*DDIM];

/* ------------------------------------------------------------ helpers      */
__device__ __forceinline__ unsigned smem_u32(const void* p) {
    unsigned a;
    asm("{ .reg .u64 t; cvta.to.shared.u64 t, %1; cvt.u32.u64 %0, t; }"
        : "=r"(a) : "l"(p));
    return a;
}
__device__ __forceinline__ void ldmx4(unsigned* r, unsigned addr) {
    asm volatile("ldmatrix.sync.aligned.m8n8.x4.shared.b16 {%0,%1,%2,%3}, [%4];"
        : "=r"(r[0]), "=r"(r[1]), "=r"(r[2]), "=r"(r[3]) : "r"(addr));
}
__device__ __forceinline__ void mma_bf16(float* c, const unsigned* a,
                                         unsigned b0, unsigned b1) {
    asm volatile("mma.sync.aligned.m16n8k16.row.col.f32.bf16.bf16.f32 "
        "{%0,%1,%2,%3}, {%4,%5,%6,%7}, {%8,%9}, {%0,%1,%2,%3};"
        : "+f"(c[0]), "+f"(c[1]), "+f"(c[2]), "+f"(c[3])
        : "r"(a[0]), "r"(a[1]), "r"(a[2]), "r"(a[3]), "r"(b0), "r"(b1));
}
__device__ __forceinline__ void cpa16(unsigned dst, const void* src) {
    asm volatile("cp.async.cg.shared.global [%0], [%1], 16;"
                 :: "r"(dst), "l"(src));
}
#define CP_COMMIT() asm volatile("cp.async.commit_group;" ::: "memory")
#define CP_WAIT(n)  asm volatile("cp.async.wait_group %0;" :: "n"(n) : "memory")

__device__ __forceinline__ float gelu_f(float x) {
    return 0.5f * x * (1.0f + erff(x * 0.70710678118654752f));
}
__device__ __forceinline__ void split2(float x, __nv_bfloat16& h, __nv_bfloat16& l) {
    h = __float2bfloat16(x);
    l = __float2bfloat16(x - __bfloat162float(h));
}

/* --------------------------------------------------------------- embedding */
__global__ void __launch_bounds__(256) embed_k(
    const int* __restrict__ x_enc, const float* __restrict__ emb,
    const float* __restrict__ pos1, const float* __restrict__ pos2,
    float* __restrict__ x1, float* __restrict__ x2)
{
    int idx = blockIdx.x * 256 + threadIdx.x;
    if (idx >= BLD*DDIM) return;
    int d   = idx & (DDIM-1);
    int bl  = idx >> 7;
    int l   = bl % LL;
    int tok = x_enc[bl];
    float v = emb[(size_t)tok*DDIM + d] + pos1[(l/25)*DDIM + d] + pos2[(l%25)*DDIM + d];
    x1[idx] = v;
    x2[idx] = v;
}

/* ---------------------------------------------------- weight split+transp. */
/* W: [L][K][N] fp32 -> Th/Tl: [L][nTot][K] bf16, cols placed at nOff       */
__global__ void __launch_bounds__(256) wsplit_k(
    const float* __restrict__ W, __nv_bfloat16* __restrict__ Th,
    __nv_bfloat16* __restrict__ Tl, int K, int N, int nOff, int nTot, int total)
{
    int idx = blockIdx.x * 256 + threadIdx.x;
    if (idx >= total) return;
    int kn = K * N;
    int l = idx / kn, r = idx - l * kn;
    int k = r / N, n = r - k * N;
    float w = W[idx];
    __nv_bfloat16 hb, lb;
    split2(w, hb, lb);
    size_t o = (size_t)l * nTot * K + (size_t)(n + nOff) * K + k;
    Th[o] = hb; Tl[o] = lb;
}

/* -------------------------------------------------------------- layernorm  */
__global__ void __launch_bounds__(128) ln_k(
    const float* __restrict__ x, const float* __restrict__ xb,
    const float* __restrict__ g, const float* __restrict__ bta,
    float* __restrict__ outf,
    __nv_bfloat16* __restrict__ outh, __nv_bfloat16* __restrict__ outl)
{
    int warp = threadIdx.x >> 5, lane = threadIdx.x & 31;
    int row  = blockIdx.x * 4 + warp;
    int off  = row * DDIM + lane * 4;
    float4 a = *(const float4*)&x[off];
    if (xb) {
        float4 c = *(const float4*)&xb[off];
        a.x = (a.x + c.x) * 0.5f; a.y = (a.y + c.y) * 0.5f;
        a.z = (a.z + c.z) * 0.5f; a.w = (a.w + c.w) * 0.5f;
    }
    float s = a.x + a.y + a.z + a.w;
    #pragma unroll
    for (int o = 16; o; o >>= 1) s += __shfl_xor_sync(0xffffffffu, s, o);
    float mu = s * (1.0f/128.0f);
    float d0 = a.x-mu, d1 = a.y-mu, d2 = a.z-mu, d3 = a.w-mu;
    float q = d0*d0 + d1*d1 + d2*d2 + d3*d3;
    #pragma unroll
    for (int o = 16; o; o >>= 1) q += __shfl_xor_sync(0xffffffffu, q, o);
    float r = rsqrtf(q * (1.0f/128.0f) + 1e-5f);
    float4 gg = *(const float4*)&g[lane*4];
    float4 bb = *(const float4*)&bta[lane*4];
    float ov[4];
    ov[0] = d0*r*gg.x + bb.x;  ov[1] = d1*r*gg.y + bb.y;
    ov[2] = d2*r*gg.z + bb.z;  ov[3] = d3*r*gg.w + bb.w;
    if (outf) {
        *(float4*)&outf[off] = make_float4(ov[0], ov[1], ov[2], ov[3]);
    }
    if (outh) {
        union { __nv_bfloat16 b[4]; uint2 u; } ph, pl;
        #pragma unroll
        for (int j = 0; j < 4; j++) split2(ov[j], ph.b[j], pl.b[j]);
        *(uint2*)&outh[off] = ph.u;
        *(uint2*)&outl[off] = pl.u;
    }
}

/* ----------------------------------------------------- HMMA bf16x3 GEMM    */
/* C[M,Ntot] = A[M,K] @ B^T, B stored [Ntot][K] (hi/lo pairs).               */
/* CTA tile 128x128, 8 warps (2x4) of 64x32, K-chunks of 32.                 */
/* cp.async 2-stage pipeline; 2 CTAs/SM; smem 2 x 4 tiles [128][32bf16]@80B. */
#define TSTRIDE 80
#define TSIZE   (128*TSTRIDE)   /* 10240 */
#define STAGE   (4*TSIZE)       /* 40960 */
#define GSMEM   (2*STAGE)       /* 81920 */

__global__ void __launch_bounds__(256, 2) mma_gemm_k(
    const __nv_bfloat16* __restrict__ Ah, const __nv_bfloat16* __restrict__ Al,
    const __nv_bfloat16* __restrict__ Bh, const __nv_bfloat16* __restrict__ Bl,
    int K, int Ntot,
    const float* __restrict__ bias, const float* __restrict__ res,
    float* __restrict__ Cf,
    __nv_bfloat16* __restrict__ Ch, __nv_bfloat16* __restrict__ Cl,
    int do_gelu)
{
    extern __shared__ char sm[];

    int tid = threadIdx.x;
    int lane = tid & 31, w = tid >> 5;
    int wr = (w >> 2) * 64;            /* warp row base in tile  */
    int wc = (w & 3) * 32;             /* warp col base in tile  */
    int rowBase = blockIdx.y * 128;
    int colBase = blockIdx.x * 128;
    int g  = lane >> 2, t4 = lane & 3;

    float acc[4][4][4];
    #pragma unroll
    for (int mi = 0; mi < 4; mi++)
        #pragma unroll
        for (int ni = 0; ni < 4; ni++)
            #pragma unroll
            for (int j = 0; j < 4; j++) acc[mi][ni][j] = 0.0f;

    int nchunks = K >> 5;
    /* per-thread fill coords: 2 x 16B per tensor (128 rows x 64 B) */
    int fr[2], fc[2];
    unsigned fso[2];
    #pragma unroll
    for (int t = 0; t < 2; t++) {
        int idx = tid + t * 256;
        fr[t] = idx >> 2;
        fc[t] = (idx & 3) * 8;
        fso[t] = fr[t] * TSTRIDE + fc[t] * 2;
    }

    auto issue = [&](int c, int st) {
        unsigned sb = smem_u32(sm + st * STAGE);
        int k0 = c << 5;
        #pragma unroll
        for (int t = 0; t < 2; t++) {
            size_t gA = (size_t)(rowBase + fr[t]) * K + k0 + fc[t];
            size_t gB = (size_t)(colBase + fr[t]) * K + k0 + fc[t];
            cpa16(sb + fso[t],             Ah + gA);
            cpa16(sb + TSIZE + fso[t],     Al + gA);
            cpa16(sb + 2*TSIZE + fso[t],   Bh + gB);
            cpa16(sb + 3*TSIZE + fso[t],   Bl + gB);
        }
        CP_COMMIT();
    };

    issue(0, 0);

    for (int c = 0; c < nchunks; c++) {
        if (c + 1 < nchunks) {
            issue(c + 1, (c + 1) & 1);
            CP_WAIT(1);
        } else {
            CP_WAIT(0);
        }
        __syncthreads();

        char* sAh = sm + (c & 1) * STAGE;
        char* sAl = sAh + TSIZE;
        char* sBh = sAh + 2*TSIZE;
        char* sBl = sAh + 3*TSIZE;

        #pragma unroll
        for (int kk = 0; kk < 2; kk++) {
            unsigned ah[4][4], al[4][4];
            #pragma unroll
            for (int mi = 0; mi < 4; mi++) {
                unsigned addr = smem_u32(sAh
                    + (wr + mi*16 + (lane & 15)) * TSTRIDE
                    + (kk*16 + (lane >> 4) * 8) * 2);
                ldmx4(ah[mi], addr);
                ldmx4(al[mi], addr + TSIZE);
            }
            #pragma unroll
            for (int ni = 0; ni < 4; ni++) {
                int n  = wc + ni*8 + g;
                int kb = (kk*16 + t4*2) * 2;
                unsigned bh0 = *(const unsigned*)(sBh + n*TSTRIDE + kb);
                unsigned bh1 = *(const unsigned*)(sBh + n*TSTRIDE + kb + 16);
                unsigned bl0 = *(const unsigned*)(sBl + n*TSTRIDE + kb);
                unsigned bl1 = *(const unsigned*)(sBl + n*TSTRIDE + kb + 16);
                #pragma unroll
                for (int mi = 0; mi < 4; mi++) {
                    mma_bf16(acc[mi][ni], ah[mi], bh0, bh1);
                    mma_bf16(acc[mi][ni], ah[mi], bl0, bl1);
                    mma_bf16(acc[mi][ni], al[mi], bh0, bh1);
                }
            }
        }
        __syncthreads();
    }

    /* epilogue */
    #pragma unroll
    for (int mi = 0; mi < 4; mi++) {
        #pragma unroll
        for (int ni = 0; ni < 4; ni++) {
            int col = colBase + wc + ni*8 + t4*2;
            float b0v = 0.f, b1v = 0.f;
            if (bias) { b0v = bias[col]; b1v = bias[col+1]; }
            #pragma unroll
            for (int half = 0; half < 2; half++) {
                int row = rowBase + wr + mi*16 + g + half*8;
                float v0 = acc[mi][ni][half*2+0] + b0v;
                float v1 = acc[mi][ni][half*2+1] + b1v;
                if (do_gelu) { v0 = gelu_f(v0); v1 = gelu_f(v1); }
                size_t co = (size_t)row * Ntot + col;
                if (res) {
                    float2 rv = *(const float2*)&res[co];
                    v0 += rv.x; v1 += rv.y;
                }
                if (Cf) *(float2*)&Cf[co] = make_float2(v0, v1);
                if (Ch) {
                    union { __nv_bfloat16 b[2]; unsigned u; } ph, pl;
                    split2(v0, ph.b[0], pl.b[0]);
                    split2(v1, ph.b[1], pl.b[1]);
                    *(unsigned*)&Ch[co] = ph.u;
                    *(unsigned*)&Cl[co] = pl.u;
                }
            }
        }
    }
}

/* --------------------------------------------------------------- attention */
/* qkv layout: [row][256], qk = cols 0..127, v = cols 128..255.              */
/* Max-free softmax: |scores| <= ~0.4 (LN-bounded), self exp(-5e4) == 0.     */
__global__ void __launch_bounds__(384) attn_k(
    const float* __restrict__ qkv,
    __nv_bfloat16* __restrict__ oh, __nv_bfloat16* __restrict__ ol)
{
    __shared__ float ks[LL][DHH];
    __shared__ float vs[LL][DHH];
    int bh = blockIdx.x;
    int b  = bh >> 3, h = bh & 7;
    int tid = threadIdx.x;
    const float* qbase = qkv + (size_t)(b*LL)*256 + h*DHH;
    const float* vbase = qbase + DDIM;

    for (int i = tid; i < LL*4; i += 384) {
        int row = i >> 2, q4 = (i & 3) * 4;
        *(float4*)&ks[row][q4] = *(const float4*)&qbase[(size_t)row*256 + q4];
        *(float4*)&vs[row][q4] = *(const float4*)&vbase[(size_t)row*256 + q4];
    }
    __syncthreads();

    int i = tid;
    float q[DHH];
    #pragma unroll
    for (int d = 0; d < DHH; d++) q[d] = ks[i][d];
    float nrm = 0.f;
    #pragma unroll
    for (int d = 0; d < DHH; d++) nrm += q[d]*q[d];
    nrm = fmaxf(sqrtf(nrm), 1e-12f);
    float inv = 1.0f / nrm;
    #pragma unroll
    for (int d = 0; d < DHH; d++) ks[i][d] = q[d] * inv;
    __syncthreads();

    float s = 0.0f;
    float acc[DHH];
    #pragma unroll
    for (int d = 0; d < DHH; d++) acc[d] = 0.0f;
    const float scale = 0.25f;
    for (int j = 0; j < i; j++) {
        float dot = 0.f;
        #pragma unroll
        for (int d = 0; d < DHH; d++) dot += q[d] * ks[j][d];
        float p = __expf(dot * scale);
        s += p;
        #pragma unroll
        for (int d = 0; d < DHH; d++) acc[d] += p * vs[j][d];
    }
    float invs;
    if (i == 0) {
        invs = 1.0f;
        #pragma unroll
        for (int d = 0; d < DHH; d++) acc[d] = vs[0][d];
    } else {
        invs = 1.0f / s;
    }
    size_t ob = (size_t)(b*LL + i)*DDIM + h*DHH;
    #pragma unroll
    for (int d = 0; d < DHH; d += 4) {
        union { __nv_bfloat16 b[4]; uint2 u; } ph, pl;
        split2(acc[d+0]*invs, ph.b[0], pl.b[0]);
        split2(acc[d+1]*invs, ph.b[1], pl.b[1]);
        split2(acc[d+2]*invs, ph.b[2], pl.b[2]);
        split2(acc[d+3]*invs, ph.b[3], pl.b[3]);
        *(uint2*)&oh[ob + d] = ph.u;
        *(uint2*)&ol[ob + d] = pl.u;
    }
}

/* --------------------------------------------- final projection (split-K)  */
__global__ void __launch_bounds__(256) proj_partial_k(
    const float* __restrict__ xf, const float* __restrict__ Wp,
    float* __restrict__ part)
{
    __shared__ float xs[64][133];
    __shared__ float ws[128][17];
    int cg = blockIdx.x;
    int sp = blockIdx.y;
    int tb = threadIdx.x & 63;
    int tc = (threadIdx.x >> 6) << 2;
    float a0=0,a1=0,a2=0,a3=0;
    for (int kc = 0; kc < KSPLIT; kc += 128) {
        int k0 = sp*KSPLIT + kc;
        for (int i = threadIdx.x; i < 2048; i += 256) {
            int bb2 = i >> 5; int q4 = (i & 31) << 2;
            float4 vv = *(const float4*)&xf[(size_t)bb2*KP + k0 + q4];
            xs[bb2][q4] = vv.x; xs[bb2][q4+1] = vv.y;
            xs[bb2][q4+2] = vv.z; xs[bb2][q4+3] = vv.w;
        }
        for (int i = threadIdx.x; i < 512; i += 256) {
            int kk = i >> 2; int c4 = (i & 3) << 2;
            float4 vv = *(const float4*)&Wp[(size_t)(k0+kk)*128 + cg*16 + c4];
            ws[kk][c4] = vv.x; ws[kk][c4+1] = vv.y;
            ws[kk][c4+2] = vv.z; ws[kk][c4+3] = vv.w;
        }
        __syncthreads();
        #pragma unroll 8
        for (int kk = 0; kk < 128; kk++) {
            float xv = xs[tb][kk];
            a0 += xv * ws[kk][tc+0];
            a1 += xv * ws[kk][tc+1];
            a2 += xv * ws[kk][tc+2];
            a3 += xv * ws[kk][tc+3];
        }
        __syncthreads();
    }
    int base = sp*(BB*128) + tb*128 + cg*16 + tc;
    part[base+0]=a0; part[base+1]=a1; part[base+2]=a2; part[base+3]=a3;
}

__global__ void __launch_bounds__(256) proj_reduce_k(
    const float* __restrict__ part, const float* __restrict__ bp,
    float* __restrict__ out)
{
    int idx = blockIdx.x * 256 + threadIdx.x;
    float s = bp[idx & 127];
    #pragma unroll
    for (int sp = 0; sp < NSPLIT; sp++) s += part[sp*(BB*128) + idx];
    out[idx] = s;
}

/* ------------------------------------------------------------------ driver */
extern "C" void kernel_launch(void* const* d_in, const int* in_sizes, int n_in,
                              void* d_out, int out_size)
{
    (void)in_sizes; (void)n_in; (void)out_size;
    const int*   x_enc = (const int*)  d_in[0];
    const float* emb   = (const float*)d_in[1];
    const float* pos1  = (const float*)d_in[2];
    const float* pos2  = (const float*)d_in[3];
    const float* ln1_g = (const float*)d_in[4];
    const float* ln1_b = (const float*)d_in[5];
    const float* Wqk   = (const float*)d_in[6];
    const float* Wv    = (const float*)d_in[7];
    const float* Wo    = (const float*)d_in[8];
    const float* bo    = (const float*)d_in[9];
    const float* ln2_g = (const float*)d_in[10];
    const float* ln2_b = (const float*)d_in[11];
    const float* W1    = (const float*)d_in[12];
    const float* b1    = (const float*)d_in[13];
    const float* W2    = (const float*)d_in[14];
    const float* b2    = (const float*)d_in[15];
    const float* lnf_g = (const float*)d_in[16];
    const float* lnf_b = (const float*)d_in[17];
    const float* Wp    = (const float*)d_in[18];
    const float* bp    = (const float*)d_in[19];

    float *x1,*x2,*h,*qkv,*part;
    cudaGetSymbolAddress((void**)&x1,  g_x1);
    cudaGetSymbolAddress((void**)&x2,  g_x2);
    cudaGetSymbolAddress((void**)&h,   g_h);
    cudaGetSymbolAddress((void**)&qkv, g_qkv);
    cudaGetSymbolAddress((void**)&part,g_part);

    __nv_bfloat16 *hh,*hl,*oh,*ol,*ah,*al;
    __nv_bfloat16 *wqvh,*wqvl,*woh,*wol,*w1h,*w1l,*w2h,*w2l;
    cudaGetSymbolAddress((void**)&hh, g_hh);   cudaGetSymbolAddress((void**)&hl, g_hl);
    cudaGetSymbolAddress((void**)&oh, g_oh);   cudaGetSymbolAddress((void**)&ol, g_ol);
    cudaGetSymbolAddress((void**)&ah, g_ah);   cudaGetSymbolAddress((void**)&al, g_al);
    cudaGetSymbolAddress((void**)&wqvh, g_wqvh); cudaGetSymbolAddress((void**)&wqvl, g_wqvl);
    cudaGetSymbolAddress((void**)&woh,  g_woh);  cudaGetSymbolAddress((void**)&wol,  g_wol);
    cudaGetSymbolAddress((void**)&w1h,  g_w1h);  cudaGetSymbolAddress((void**)&w1l,  g_w1l);
    cudaGetSymbolAddress((void**)&w2h,  g_w2h);  cudaGetSymbolAddress((void**)&w2l,  g_w2l);

    cudaFuncSetAttribute(mma_gemm_k, cudaFuncAttributeMaxDynamicSharedMemorySize, GSMEM);

    int t1 = NDEPTH*DDIM*DDIM;
    int t2 = NDEPTH*DDIM*FFD;

    dim3 gD(1, BLD/128);   /* Ntot=128 */
    dim3 gQ(2, BLD/128);   /* Ntot=256 (fused qkv) */
    dim3 gF(4, BLD/128);   /* Ntot=512 */

    /* launch order puts the first mma_gemm_k at launch #5 for ncu (-s 5) */
    wsplit_k<<<(t1+255)/256, 256>>>(Wqk, wqvh, wqvl, DDIM, DDIM, 0,    2*DDIM, t1); /* 1 */
    wsplit_k<<<(t1+255)/256, 256>>>(Wv,  wqvh, wqvl, DDIM, DDIM, DDIM, 2*DDIM, t1); /* 2 */
    embed_k<<<(BLD*DDIM)/256, 256>>>(x_enc, emb, pos1, pos2, x1, x2);               /* 3 */
    ln_k<<<BLD/4, 128>>>(x2, nullptr, ln1_g, ln1_b, nullptr, hh, hl);               /* 4 */
    mma_gemm_k<<<gQ, 256, GSMEM>>>(hh, hl, wqvh, wqvl,                              /* 5 */
                                   DDIM, 2*DDIM, nullptr, nullptr, qkv,
                                   nullptr, nullptr, 0);
    wsplit_k<<<(t1+255)/256, 256>>>(Wo,  woh,  wol,  DDIM, DDIM, 0, DDIM, t1);      /* 6 */
    wsplit_k<<<(t2+255)/256, 256>>>(W1,  w1h,  w1l,  DDIM, FFD,  0, FFD,  t2);      /* 7 */
    wsplit_k<<<(t2+255)/256, 256>>>(W2,  w2h,  w2l,  FFD,  DDIM, 0, DDIM, t2);      /* 8 */

    for (int d = 0; d < NDEPTH; d++) {
        size_t wsq = (size_t)d*DDIM*DDIM;
        if (d > 0) {
            ln_k<<<BLD/4, 128>>>(x2, nullptr, ln1_g + d*DDIM, ln1_b + d*DDIM,
                                 nullptr, hh, hl);
            mma_gemm_k<<<gQ, 256, GSMEM>>>(hh, hl,
                                           wqvh + (size_t)d*2*DDIM*DDIM,
                                           wqvl + (size_t)d*2*DDIM*DDIM,
                                           DDIM, 2*DDIM, nullptr, nullptr, qkv,
                                           nullptr, nullptr, 0);
        }
        attn_k<<<BB*HH, 384>>>(qkv, oh, ol);
        /* x1 = x1 + o@Wo + bo */
        mma_gemm_k<<<gD, 256, GSMEM>>>(oh, ol, woh + wsq, wol + wsq,
                                       DDIM, DDIM, bo + d*DDIM, x1, x1,
                                       nullptr, nullptr, 0);
        ln_k<<<BLD/4, 128>>>(x1, nullptr, ln2_g + d*DDIM, ln2_b + d*DDIM,
                             nullptr, hh, hl);
        /* a = gelu(h@W1 + b1) -> split */
        mma_gemm_k<<<gF, 256, GSMEM>>>(hh, hl,
                                       w1h + (size_t)d*DDIM*FFD, w1l + (size_t)d*DDIM*FFD,
                                       DDIM, FFD, b1 + d*FFD, nullptr, nullptr,
                                       ah, al, 1);
        /* x2 = x2 + a@W2 + b2 */
        mma_gemm_k<<<gD, 256, GSMEM>>>(ah, al,
                                       w2h + (size_t)d*FFD*DDIM, w2l + (size_t)d*FFD*DDIM,
                                       FFD, DDIM, b2 + d*DDIM, x2, x2,
                                       nullptr, nullptr, 0);
    }

    ln_k<<<BLD/4, 128>>>(x1, x2, lnf_g, lnf_b, h, nullptr, nullptr);
    dim3 gp(8, NSPLIT);
    proj_partial_k<<<gp, 256>>>(h, Wp, part);
    proj_reduce_k<<<NSPLIT, 256>>>(part, bp, (float*)d_out);
}

// round 9
// speedup vs baseline: 1.5278x; 1.5278x over previous
#include <cuda_runtime.h>
#include <cuda_bf16.h>
#include <stdint.h>
#include <math.h>

#define BB   64
#define LL   384
#define DDIM 128
#define HH   8
#define DHH  16
#define NDEPTH 6
#define FFD  512
#define BLD  (BB*LL)          /* 24576 rows */
#define KP   (LL*DDIM)        /* 49152     */
#define NSPLIT 32
#define KSPLIT (KP/NSPLIT)    /* 1536 */

/* ------------------------------------------------------------------ scratch */
__device__ float g_x1[BLD*DDIM];
__device__ float g_x2[BLD*DDIM];
__device__ float g_h [BLD*DDIM];          /* fp32 (final LN -> proj) */
__device__ float g_qkv[BLD*2*DDIM];       /* fused qk|v output [row][256] */
__device__ float g_part[NSPLIT*BB*128];

__device__ __nv_bfloat16 g_hh[BLD*DDIM];  /* LN output split */
__device__ __nv_bfloat16 g_hl[BLD*DDIM];
__device__ __nv_bfloat16 g_oh[BLD*DDIM];  /* attention output split */
__device__ __nv_bfloat16 g_ol[BLD*DDIM];
__device__ __nv_bfloat16 g_ah[BLD*FFD];   /* FF1 output split */
__device__ __nv_bfloat16 g_al[BLD*FFD];

/* transposed + split weights: [layer][N][K] */
__device__ __nv_bfloat16 g_wqvh[NDEPTH*2*DDIM*DDIM], g_wqvl[NDEPTH*2*DDIM*DDIM];
__device__ __nv_bfloat16 g_woh [NDEPTH*DDIM*DDIM],   g_wol [NDEPTH*DDIM*DDIM];
__device__ __nv_bfloat16 g_w1h [NDEPTH*DDIM*FFD],    g_w1l [NDEPTH*DDIM*FFD];
__device__ __nv_bfloat16 g_w2h [NDEPTH*FFD*DDIM],    g_w2l [NDEPTH*FFD*DDIM];

/* ------------------------------------------------------------ helpers      */
__device__ __forceinline__ unsigned smem_u32(const void* p) {
    unsigned a;
    asm("{ .reg .u64 t; cvta.to.shared.u64 t, %1; cvt.u32.u64 %0, t; }"
        : "=r"(a) : "l"(p));
    return a;
}
__device__ __forceinline__ void ldmx4(unsigned* r, unsigned addr) {
    asm volatile("ldmatrix.sync.aligned.m8n8.x4.shared.b16 {%0,%1,%2,%3}, [%4];"
        : "=r"(r[0]), "=r"(r[1]), "=r"(r[2]), "=r"(r[3]) : "r"(addr));
}
__device__ __forceinline__ void mma_bf16(float* c, const unsigned* a,
                                         unsigned b0, unsigned b1) {
    asm volatile("mma.sync.aligned.m16n8k16.row.col.f32.bf16.bf16.f32 "
        "{%0,%1,%2,%3}, {%4,%5,%6,%7}, {%8,%9}, {%0,%1,%2,%3};"
        : "+f"(c[0]), "+f"(c[1]), "+f"(c[2]), "+f"(c[3])
        : "r"(a[0]), "r"(a[1]), "r"(a[2]), "r"(a[3]), "r"(b0), "r"(b1));
}
__device__ __forceinline__ void cpa16(unsigned dst, const void* src) {
    asm volatile("cp.async.cg.shared.global [%0], [%1], 16;"
                 :: "r"(dst), "l"(src));
}
#define CP_COMMIT() asm volatile("cp.async.commit_group;" ::: "memory")
#define CP_WAIT(n)  asm volatile("cp.async.wait_group %0;" :: "n"(n) : "memory")

__device__ __forceinline__ float gelu_f(float x) {
    return 0.5f * x * (1.0f + erff(x * 0.70710678118654752f));
}
__device__ __forceinline__ void split2(float x, __nv_bfloat16& h, __nv_bfloat16& l) {
    h = __float2bfloat16(x);
    l = __float2bfloat16(x - __bfloat162float(h));
}

/* --------------------------------------------------------------- embedding */
__global__ void __launch_bounds__(256) embed_k(
    const int* __restrict__ x_enc, const float* __restrict__ emb,
    const float* __restrict__ pos1, const float* __restrict__ pos2,
    float* __restrict__ x1, float* __restrict__ x2)
{
    int idx = blockIdx.x * 256 + threadIdx.x;
    if (idx >= BLD*DDIM) return;
    int d   = idx & (DDIM-1);
    int bl  = idx >> 7;
    int l   = bl % LL;
    int tok = x_enc[bl];
    float v = emb[(size_t)tok*DDIM + d] + pos1[(l/25)*DDIM + d] + pos2[(l%25)*DDIM + d];
    x1[idx] = v;
    x2[idx] = v;
}

/* ---------------------------------------------------- weight split+transp. */
/* W: [L][K][N] fp32 -> Th/Tl: [L][nTot][K] bf16, cols placed at nOff       */
__global__ void __launch_bounds__(256) wsplit_k(
    const float* __restrict__ W, __nv_bfloat16* __restrict__ Th,
    __nv_bfloat16* __restrict__ Tl, int K, int N, int nOff, int nTot, int total)
{
    int idx = blockIdx.x * 256 + threadIdx.x;
    if (idx >= total) return;
    int kn = K * N;
    int l = idx / kn, r = idx - l * kn;
    int k = r / N, n = r - k * N;
    float w = W[idx];
    __nv_bfloat16 hb, lb;
    split2(w, hb, lb);
    size_t o = (size_t)l * nTot * K + (size_t)(n + nOff) * K + k;
    Th[o] = hb; Tl[o] = lb;
}

/* combined Wqk|Wv split into the fused [2*DDIM][DDIM] layout */
__global__ void __launch_bounds__(256) wsplit_qkv_k(
    const float* __restrict__ Wqk, const float* __restrict__ Wv,
    __nv_bfloat16* __restrict__ Th, __nv_bfloat16* __restrict__ Tl)
{
    const int t1 = NDEPTH*DDIM*DDIM;
    int idx = blockIdx.x * 256 + threadIdx.x;
    if (idx >= 2*t1) return;
    const float* W = (idx < t1) ? Wqk : Wv;
    int nOff = (idx < t1) ? 0 : DDIM;
    int i = (idx < t1) ? idx : idx - t1;
    int kn = DDIM * DDIM;
    int l = i / kn, r = i - l * kn;
    int k = r / DDIM, n = r - k * DDIM;
    float w = W[i];
    __nv_bfloat16 hb, lb;
    split2(w, hb, lb);
    size_t o = (size_t)l * 2*DDIM*DDIM + (size_t)(n + nOff) * DDIM + k;
    Th[o] = hb; Tl[o] = lb;
}

/* -------------------------------------------------------------- layernorm  */
__global__ void __launch_bounds__(128) ln_k(
    const float* __restrict__ x, const float* __restrict__ xb,
    const float* __restrict__ g, const float* __restrict__ bta,
    float* __restrict__ outf,
    __nv_bfloat16* __restrict__ outh, __nv_bfloat16* __restrict__ outl)
{
    int warp = threadIdx.x >> 5, lane = threadIdx.x & 31;
    int row  = blockIdx.x * 4 + warp;
    int off  = row * DDIM + lane * 4;
    float4 a = *(const float4*)&x[off];
    if (xb) {
        float4 c = *(const float4*)&xb[off];
        a.x = (a.x + c.x) * 0.5f; a.y = (a.y + c.y) * 0.5f;
        a.z = (a.z + c.z) * 0.5f; a.w = (a.w + c.w) * 0.5f;
    }
    float s = a.x + a.y + a.z + a.w;
    #pragma unroll
    for (int o = 16; o; o >>= 1) s += __shfl_xor_sync(0xffffffffu, s, o);
    float mu = s * (1.0f/128.0f);
    float d0 = a.x-mu, d1 = a.y-mu, d2 = a.z-mu, d3 = a.w-mu;
    float q = d0*d0 + d1*d1 + d2*d2 + d3*d3;
    #pragma unroll
    for (int o = 16; o; o >>= 1) q += __shfl_xor_sync(0xffffffffu, q, o);
    float r = rsqrtf(q * (1.0f/128.0f) + 1e-5f);
    float4 gg = *(const float4*)&g[lane*4];
    float4 bb = *(const float4*)&bta[lane*4];
    float ov[4];
    ov[0] = d0*r*gg.x + bb.x;  ov[1] = d1*r*gg.y + bb.y;
    ov[2] = d2*r*gg.z + bb.z;  ov[3] = d3*r*gg.w + bb.w;
    if (outf) {
        *(float4*)&outf[off] = make_float4(ov[0], ov[1], ov[2], ov[3]);
    }
    if (outh) {
        union { __nv_bfloat16 b[4]; uint2 u; } ph, pl;
        #pragma unroll
        for (int j = 0; j < 4; j++) split2(ov[j], ph.b[j], pl.b[j]);
        *(uint2*)&outh[off] = ph.u;
        *(uint2*)&outl[off] = pl.u;
    }
}

/* ----------------------------------------------------- HMMA bf16x3 GEMM    */
/* C[M,Ntot] = A[M,K] @ B^T, B stored [Ntot][K] (hi/lo pairs).               */
/* CTA tile 128x128, 8 warps (2x4) of 64x32, K-chunks of 64.                 */
/* cp.async 2-stage pipeline; smem: 2 stages x 4 tiles [128][64bf16]@144B.   */
#define TSTRIDE 144
#define TSIZE   (128*TSTRIDE)   /* 18432 */
#define STAGE   (4*TSIZE)       /* 73728 */
#define GSMEM   (2*STAGE)       /* 147456 */

__global__ void __launch_bounds__(256) mma_gemm_k(
    const __nv_bfloat16* __restrict__ Ah, const __nv_bfloat16* __restrict__ Al,
    const __nv_bfloat16* __restrict__ Bh, const __nv_bfloat16* __restrict__ Bl,
    int K, int Ntot,
    const float* __restrict__ bias, const float* __restrict__ res,
    float* __restrict__ Cf,
    __nv_bfloat16* __restrict__ Ch, __nv_bfloat16* __restrict__ Cl,
    int do_gelu)
{
    extern __shared__ char sm[];

    int tid = threadIdx.x;
    int lane = tid & 31, w = tid >> 5;
    int wr = (w >> 2) * 64;            /* warp row base in tile  */
    int wc = (w & 3) * 32;             /* warp col base in tile  */
    int rowBase = blockIdx.y * 128;
    int colBase = blockIdx.x * 128;
    int g  = lane >> 2, t4 = lane & 3;

    float acc[4][4][4];
    #pragma unroll
    for (int mi = 0; mi < 4; mi++)
        #pragma unroll
        for (int ni = 0; ni < 4; ni++)
            #pragma unroll
            for (int j = 0; j < 4; j++) acc[mi][ni][j] = 0.0f;

    int nchunks = K >> 6;
    /* per-thread fill coords: 4 chunks of 16B per tensor */
    int fr[4], fc[4];
    unsigned fso[4];
    #pragma unroll
    for (int t = 0; t < 4; t++) {
        int idx = tid + t * 256;
        fr[t] = idx >> 3;
        fc[t] = (idx & 7) * 8;
        fso[t] = fr[t] * TSTRIDE + fc[t] * 2;
    }

    auto issue = [&](int c, int st) {
        unsigned sb = smem_u32(sm + st * STAGE);
        int k0 = c << 6;
        #pragma unroll
        for (int t = 0; t < 4; t++) {
            size_t gA = (size_t)(rowBase + fr[t]) * K + k0 + fc[t];
            size_t gB = (size_t)(colBase + fr[t]) * K + k0 + fc[t];
            cpa16(sb + fso[t],             Ah + gA);
            cpa16(sb + TSIZE + fso[t],     Al + gA);
            cpa16(sb + 2*TSIZE + fso[t],   Bh + gB);
            cpa16(sb + 3*TSIZE + fso[t],   Bl + gB);
        }
        CP_COMMIT();
    };

    issue(0, 0);

    for (int c = 0; c < nchunks; c++) {
        if (c + 1 < nchunks) {
            issue(c + 1, (c + 1) & 1);
            CP_WAIT(1);
        } else {
            CP_WAIT(0);
        }
        __syncthreads();

        char* sAh = sm + (c & 1) * STAGE;
        char* sAl = sAh + TSIZE;
        char* sBh = sAh + 2*TSIZE;
        char* sBl = sAh + 3*TSIZE;

        #pragma unroll
        for (int kk = 0; kk < 4; kk++) {
            unsigned ah[4][4], al[4][4];
            #pragma unroll
            for (int mi = 0; mi < 4; mi++) {
                unsigned addr = smem_u32(sAh
                    + (wr + mi*16 + (lane & 15)) * TSTRIDE
                    + (kk*16 + (lane >> 4) * 8) * 2);
                ldmx4(ah[mi], addr);
                ldmx4(al[mi], addr + TSIZE);
            }
            #pragma unroll
            for (int ni = 0; ni < 4; ni++) {
                int n  = wc + ni*8 + g;
                int kb = (kk*16 + t4*2) * 2;
                unsigned bh0 = *(const unsigned*)(sBh + n*TSTRIDE + kb);
                unsigned bh1 = *(const unsigned*)(sBh + n*TSTRIDE + kb + 16);
                unsigned bl0 = *(const unsigned*)(sBl + n*TSTRIDE + kb);
                unsigned bl1 = *(const unsigned*)(sBl + n*TSTRIDE + kb + 16);
                #pragma unroll
                for (int mi = 0; mi < 4; mi++) {
                    mma_bf16(acc[mi][ni], ah[mi], bh0, bh1);
                    mma_bf16(acc[mi][ni], ah[mi], bl0, bl1);
                    mma_bf16(acc[mi][ni], al[mi], bh0, bh1);
                }
            }
        }
        __syncthreads();
    }

    /* epilogue */
    #pragma unroll
    for (int mi = 0; mi < 4; mi++) {
        #pragma unroll
        for (int ni = 0; ni < 4; ni++) {
            int col = colBase + wc + ni*8 + t4*2;
            float b0v = 0.f, b1v = 0.f;
            if (bias) { b0v = bias[col]; b1v = bias[col+1]; }
            #pragma unroll
            for (int half = 0; half < 2; half++) {
                int row = rowBase + wr + mi*16 + g + half*8;
                float v0 = acc[mi][ni][half*2+0] + b0v;
                float v1 = acc[mi][ni][half*2+1] + b1v;
                if (do_gelu) { v0 = gelu_f(v0); v1 = gelu_f(v1); }
                size_t co = (size_t)row * Ntot + col;
                if (res) {
                    float2 rv = *(const float2*)&res[co];
                    v0 += rv.x; v1 += rv.y;
                }
                if (Cf) *(float2*)&Cf[co] = make_float2(v0, v1);
                if (Ch) {
                    union { __nv_bfloat16 b[2]; unsigned u; } ph, pl;
                    split2(v0, ph.b[0], pl.b[0]);
                    split2(v1, ph.b[1], pl.b[1]);
                    *(unsigned*)&Ch[co] = ph.u;
                    *(unsigned*)&Cl[co] = pl.u;
                }
            }
        }
    }
}

/* --------------------------------------------------------------- attention */
/* qkv layout: [row][256], qk = cols 0..127, v = cols 128..255.              */
/* Max-free softmax: |scores| bounded (LN-bounded), self exp(-5e4) == 0.     */
__global__ void __launch_bounds__(384) attn_k(
    const float* __restrict__ qkv,
    __nv_bfloat16* __restrict__ oh, __nv_bfloat16* __restrict__ ol)
{
    __shared__ float ks[LL][DHH];
    __shared__ float vs[LL][DHH];
    int bh = blockIdx.x;
    int b  = bh >> 3, h = bh & 7;
    int tid = threadIdx.x;
    const float* qbase = qkv + (size_t)(b*LL)*256 + h*DHH;
    const float* vbase = qbase + DDIM;

    for (int i = tid; i < LL*4; i += 384) {
        int row = i >> 2, q4 = (i & 3) * 4;
        *(float4*)&ks[row][q4] = *(const float4*)&qbase[(size_t)row*256 + q4];
        *(float4*)&vs[row][q4] = *(const float4*)&vbase[(size_t)row*256 + q4];
    }
    __syncthreads();

    int i = tid;
    float q[DHH];
    #pragma unroll
    for (int d = 0; d < DHH; d++) q[d] = ks[i][d];
    float nrm = 0.f;
    #pragma unroll
    for (int d = 0; d < DHH; d++) nrm += q[d]*q[d];
    nrm = fmaxf(sqrtf(nrm), 1e-12f);
    float inv = 1.0f / nrm;
    #pragma unroll
    for (int d = 0; d < DHH; d++) ks[i][d] = q[d] * inv;
    __syncthreads();

    float s = 0.0f;
    float acc[DHH];
    #pragma unroll
    for (int d = 0; d < DHH; d++) acc[d] = 0.0f;
    const float scale = 0.25f;
    for (int j = 0; j < i; j++) {
        float dot = 0.f;
        #pragma unroll
        for (int d = 0; d < DHH; d++) dot += q[d] * ks[j][d];
        float p = __expf(dot * scale);
        s += p;
        #pragma unroll
        for (int d = 0; d < DHH; d++) acc[d] += p * vs[j][d];
    }
    float invs;
    if (i == 0) {
        invs = 1.0f;
        #pragma unroll
        for (int d = 0; d < DHH; d++) acc[d] = vs[0][d];
    } else {
        invs = 1.0f / s;
    }
    size_t ob = (size_t)(b*LL + i)*DDIM + h*DHH;
    #pragma unroll
    for (int d = 0; d < DHH; d += 4) {
        union { __nv_bfloat16 b[4]; uint2 u; } ph, pl;
        split2(acc[d+0]*invs, ph.b[0], pl.b[0]);
        split2(acc[d+1]*invs, ph.b[1], pl.b[1]);
        split2(acc[d+2]*invs, ph.b[2], pl.b[2]);
        split2(acc[d+3]*invs, ph.b[3], pl.b[3]);
        *(uint2*)&oh[ob + d] = ph.u;
        *(uint2*)&ol[ob + d] = pl.u;
    }
}

/* --------------------------------------------- final projection (split-K)  */
__global__ void __launch_bounds__(256) proj_partial_k(
    const float* __restrict__ xf, const float* __restrict__ Wp,
    float* __restrict__ part)
{
    __shared__ float xs[64][133];
    __shared__ float ws[128][17];
    int cg = blockIdx.x;
    int sp = blockIdx.y;
    int tb = threadIdx.x & 63;
    int tc = (threadIdx.x >> 6) << 2;
    float a0=0,a1=0,a2=0,a3=0;
    for (int kc = 0; kc < KSPLIT; kc += 128) {
        int k0 = sp*KSPLIT + kc;
        for (int i = threadIdx.x; i < 2048; i += 256) {
            int bb2 = i >> 5; int q4 = (i & 31) << 2;
            float4 vv = *(const float4*)&xf[(size_t)bb2*KP + k0 + q4];
            xs[bb2][q4] = vv.x; xs[bb2][q4+1] = vv.y;
            xs[bb2][q4+2] = vv.z; xs[bb2][q4+3] = vv.w;
        }
        for (int i = threadIdx.x; i < 512; i += 256) {
            int kk = i >> 2; int c4 = (i & 3) << 2;
            float4 vv = *(const float4*)&Wp[(size_t)(k0+kk)*128 + cg*16 + c4];
            ws[kk][c4] = vv.x; ws[kk][c4+1] = vv.y;
            ws[kk][c4+2] = vv.z; ws[kk][c4+3] = vv.w;
        }
        __syncthreads();
        #pragma unroll 8
        for (int kk = 0; kk < 128; kk++) {
            float xv = xs[tb][kk];
            a0 += xv * ws[kk][tc+0];
            a1 += xv * ws[kk][tc+1];
            a2 += xv * ws[kk][tc+2];
            a3 += xv * ws[kk][tc+3];
        }
        __syncthreads();
    }
    int base = sp*(BB*128) + tb*128 + cg*16 + tc;
    part[base+0]=a0; part[base+1]=a1; part[base+2]=a2; part[base+3]=a3;
}

__global__ void __launch_bounds__(256) proj_reduce_k(
    const float* __restrict__ part, const float* __restrict__ bp,
    float* __restrict__ out)
{
    int idx = blockIdx.x * 256 + threadIdx.x;
    float s = bp[idx & 127];
    #pragma unroll
    for (int sp = 0; sp < NSPLIT; sp++) s += part[sp*(BB*128) + idx];
    out[idx] = s;
}

/* ------------------------------------------------------------------ driver */
extern "C" void kernel_launch(void* const* d_in, const int* in_sizes, int n_in,
                              void* d_out, int out_size)
{
    (void)in_sizes; (void)n_in; (void)out_size;
    const int*   x_enc = (const int*)  d_in[0];
    const float* emb   = (const float*)d_in[1];
    const float* pos1  = (const float*)d_in[2];
    const float* pos2  = (const float*)d_in[3];
    const float* ln1_g = (const float*)d_in[4];
    const float* ln1_b = (const float*)d_in[5];
    const float* Wqk   = (const float*)d_in[6];
    const float* Wv    = (const float*)d_in[7];
    const float* Wo    = (const float*)d_in[8];
    const float* bo    = (const float*)d_in[9];
    const float* ln2_g = (const float*)d_in[10];
    const float* ln2_b = (const float*)d_in[11];
    const float* W1    = (const float*)d_in[12];
    const float* b1    = (const float*)d_in[13];
    const float* W2    = (const float*)d_in[14];
    const float* b2    = (const float*)d_in[15];
    const float* lnf_g = (const float*)d_in[16];
    const float* lnf_b = (const float*)d_in[17];
    const float* Wp    = (const float*)d_in[18];
    const float* bp    = (const float*)d_in[19];

    float *x1,*x2,*h,*qkv,*part;
    cudaGetSymbolAddress((void**)&x1,  g_x1);
    cudaGetSymbolAddress((void**)&x2,  g_x2);
    cudaGetSymbolAddress((void**)&h,   g_h);
    cudaGetSymbolAddress((void**)&qkv, g_qkv);
    cudaGetSymbolAddress((void**)&part,g_part);

    __nv_bfloat16 *hh,*hl,*oh,*ol,*ah,*al;
    __nv_bfloat16 *wqvh,*wqvl,*woh,*wol,*w1h,*w1l,*w2h,*w2l;
    cudaGetSymbolAddress((void**)&hh, g_hh);   cudaGetSymbolAddress((void**)&hl, g_hl);
    cudaGetSymbolAddress((void**)&oh, g_oh);   cudaGetSymbolAddress((void**)&ol, g_ol);
    cudaGetSymbolAddress((void**)&ah, g_ah);   cudaGetSymbolAddress((void**)&al, g_al);
    cudaGetSymbolAddress((void**)&wqvh, g_wqvh); cudaGetSymbolAddress((void**)&wqvl, g_wqvl);
    cudaGetSymbolAddress((void**)&woh,  g_woh);  cudaGetSymbolAddress((void**)&wol,  g_wol);
    cudaGetSymbolAddress((void**)&w1h,  g_w1h);  cudaGetSymbolAddress((void**)&w1l,  g_w1l);
    cudaGetSymbolAddress((void**)&w2h,  g_w2h);  cudaGetSymbolAddress((void**)&w2l,  g_w2l);

    cudaFuncSetAttribute(mma_gemm_k, cudaFuncAttributeMaxDynamicSharedMemorySize, GSMEM);

    int t1 = NDEPTH*DDIM*DDIM;
    int t2 = NDEPTH*DDIM*FFD;

    dim3 gD(1, BLD/128);   /* Ntot=128 */
    dim3 gQ(2, BLD/128);   /* Ntot=256 (fused qkv) */
    dim3 gF(4, BLD/128);   /* Ntot=512 */

    /* launch order puts the first mma_gemm_k at launch #4 (ncu captures #4) */
    embed_k<<<(BLD*DDIM)/256, 256>>>(x_enc, emb, pos1, pos2, x1, x2);               /* 1 */
    ln_k<<<BLD/4, 128>>>(x2, nullptr, ln1_g, ln1_b, nullptr, hh, hl);               /* 2 */
    wsplit_qkv_k<<<(2*t1+255)/256, 256>>>(Wqk, Wv, wqvh, wqvl);                     /* 3 */
    mma_gemm_k<<<gQ, 256, GSMEM>>>(hh, hl, wqvh, wqvl,                              /* 4 */
                                   DDIM, 2*DDIM, nullptr, nullptr, qkv,
                                   nullptr, nullptr, 0);
    wsplit_k<<<(t1+255)/256, 256>>>(Wo,  woh,  wol,  DDIM, DDIM, 0, DDIM, t1);      /* 5 */
    wsplit_k<<<(t2+255)/256, 256>>>(W1,  w1h,  w1l,  DDIM, FFD,  0, FFD,  t2);      /* 6 */
    wsplit_k<<<(t2+255)/256, 256>>>(W2,  w2h,  w2l,  FFD,  DDIM, 0, DDIM, t2);      /* 7 */

    for (int d = 0; d < NDEPTH; d++) {
        size_t wsq = (size_t)d*DDIM*DDIM;
        if (d > 0) {
            ln_k<<<BLD/4, 128>>>(x2, nullptr, ln1_g + d*DDIM, ln1_b + d*DDIM,
                                 nullptr, hh, hl);
            mma_gemm_k<<<gQ, 256, GSMEM>>>(hh, hl,
                                           wqvh + (size_t)d*2*DDIM*DDIM,
                                           wqvl + (size_t)d*2*DDIM*DDIM,
                                           DDIM, 2*DDIM, nullptr, nullptr, qkv,
                                           nullptr, nullptr, 0);
        }
        attn_k<<<BB*HH, 384>>>(qkv, oh, ol);
        /* x1 = x1 + o@Wo + bo */
        mma_gemm_k<<<gD, 256, GSMEM>>>(oh, ol, woh + wsq, wol + wsq,
                                       DDIM, DDIM, bo + d*DDIM, x1, x1,
                                       nullptr, nullptr, 0);
        ln_k<<<BLD/4, 128>>>(x1, nullptr, ln2_g + d*DDIM, ln2_b + d*DDIM,
                             nullptr, hh, hl);
        /* a = gelu(h@W1 + b1) -> split */
        mma_gemm_k<<<gF, 256, GSMEM>>>(hh, hl,
                                       w1h + (size_t)d*DDIM*FFD, w1l + (size_t)d*DDIM*FFD,
                                       DDIM, FFD, b1 + d*FFD, nullptr, nullptr,
                                       ah, al, 1);
        /* x2 = x2 + a@W2 + b2 */
        mma_gemm_k<<<gD, 256, GSMEM>>>(ah, al,
                                       w2h + (size_t)d*FFD*DDIM, w2l + (size_t)d*FFD*DDIM,
                                       FFD, DDIM, b2 + d*DDIM, x2, x2,
                                       nullptr, nullptr, 0);
    }

    ln_k<<<BLD/4, 128>>>(x1, x2, lnf_g, lnf_b, h, nullptr, nullptr);
    dim3 gp(8, NSPLIT);
    proj_partial_k<<<gp, 256>>>(h, Wp, part);
    proj_reduce_k<<<NSPLIT, 256>>>(part, bp, (float*)d_out);
}

// round 12
// speedup vs baseline: 1.5357x; 1.0052x over previous
#include <cuda_runtime.h>
#include <cuda_bf16.h>
#include <stdint.h>
#include <math.h>

#define BB   64
#define LL   384
#define DDIM 128
#define HH   8
#define DHH  16
#define NDEPTH 6
#define FFD  512
#define BLD  (BB*LL)          /* 24576 rows */
#define KP   (LL*DDIM)        /* 49152     */
#define NSPLIT 32
#define KSPLIT (KP/NSPLIT)    /* 1536 */

/* ------------------------------------------------------------------ scratch */
__device__ float g_x1[BLD*DDIM];
__device__ float g_x2[BLD*DDIM];
__device__ float g_h [BLD*DDIM];          /* fp32 (final LN -> proj) */
__device__ float g_qkv[BLD*2*DDIM];       /* fused qk|v output [row][256] */
__device__ float g_part[NSPLIT*BB*128];

__device__ __nv_bfloat16 g_hh[BLD*DDIM];  /* LN output split */
__device__ __nv_bfloat16 g_hl[BLD*DDIM];
__device__ __nv_bfloat16 g_oh[BLD*DDIM];  /* attention output split */
__device__ __nv_bfloat16 g_ol[BLD*DDIM];
__device__ __nv_bfloat16 g_ah[BLD*FFD];   /* FF1 output split */
__device__ __nv_bfloat16 g_al[BLD*FFD];

/* transposed + split weights: [layer][N][K] */
__device__ __nv_bfloat16 g_wqvh[NDEPTH*2*DDIM*DDIM], g_wqvl[NDEPTH*2*DDIM*DDIM];
__device__ __nv_bfloat16 g_woh [NDEPTH*DDIM*DDIM],   g_wol [NDEPTH*DDIM*DDIM];
__device__ __nv_bfloat16 g_w1h [NDEPTH*DDIM*FFD],    g_w1l [NDEPTH*DDIM*FFD];
__device__ __nv_bfloat16 g_w2h [NDEPTH*FFD*DDIM],    g_w2l [NDEPTH*FFD*DDIM];

/* ------------------------------------------------------------ helpers      */
__device__ __forceinline__ unsigned smem_u32(const void* p) {
    unsigned a;
    asm("{ .reg .u64 t; cvta.to.shared.u64 t, %1; cvt.u32.u64 %0, t; }"
        : "=r"(a) : "l"(p));
    return a;
}
__device__ __forceinline__ void ldmx4(unsigned* r, unsigned addr) {
    asm volatile("ldmatrix.sync.aligned.m8n8.x4.shared.b16 {%0,%1,%2,%3}, [%4];"
        : "=r"(r[0]), "=r"(r[1]), "=r"(r[2]), "=r"(r[3]) : "r"(addr));
}
__device__ __forceinline__ void mma_bf16(float* c, const unsigned* a,
                                         unsigned b0, unsigned b1) {
    asm volatile("mma.sync.aligned.m16n8k16.row.col.f32.bf16.bf16.f32 "
        "{%0,%1,%2,%3}, {%4,%5,%6,%7}, {%8,%9}, {%0,%1,%2,%3};"
        : "+f"(c[0]), "+f"(c[1]), "+f"(c[2]), "+f"(c[3])
        : "r"(a[0]), "r"(a[1]), "r"(a[2]), "r"(a[3]), "r"(b0), "r"(b1));
}
__device__ __forceinline__ void cpa16(unsigned dst, const void* src) {
    asm volatile("cp.async.cg.shared.global [%0], [%1], 16;"
                 :: "r"(dst), "l"(src));
}
#define CP_COMMIT() asm volatile("cp.async.commit_group;" ::: "memory")
#define CP_WAIT(n)  asm volatile("cp.async.wait_group %0;" :: "n"(n) : "memory")

__device__ __forceinline__ float gelu_f(float x) {
    return 0.5f * x * (1.0f + erff(x * 0.70710678118654752f));
}
__device__ __forceinline__ void split2(float x, __nv_bfloat16& h, __nv_bfloat16& l) {
    h = __float2bfloat16(x);
    l = __float2bfloat16(x - __bfloat162float(h));
}

/* --------------------------------------------------------------- embedding */
__global__ void __launch_bounds__(256) embed_k(
    const int* __restrict__ x_enc, const float* __restrict__ emb,
    const float* __restrict__ pos1, const float* __restrict__ pos2,
    float* __restrict__ x1, float* __restrict__ x2)
{
    int idx = blockIdx.x * 256 + threadIdx.x;
    if (idx >= BLD*DDIM) return;
    int d   = idx & (DDIM-1);
    int bl  = idx >> 7;
    int l   = bl % LL;
    int tok = x_enc[bl];
    float v = emb[(size_t)tok*DDIM + d] + pos1[(l/25)*DDIM + d] + pos2[(l%25)*DDIM + d];
    x1[idx] = v;
    x2[idx] = v;
}

/* ---------------------------------------------------- weight split+transp. */
/* W: [L][K][N] fp32 -> Th/Tl: [L][nTot][K] bf16, cols placed at nOff       */
__global__ void __launch_bounds__(256) wsplit_k(
    const float* __restrict__ W, __nv_bfloat16* __restrict__ Th,
    __nv_bfloat16* __restrict__ Tl, int K, int N, int nOff, int nTot, int total)
{
    int idx = blockIdx.x * 256 + threadIdx.x;
    if (idx >= total) return;
    int kn = K * N;
    int l = idx / kn, r = idx - l * kn;
    int k = r / N, n = r - k * N;
    float w = W[idx];
    __nv_bfloat16 hb, lb;
    split2(w, hb, lb);
    size_t o = (size_t)l * nTot * K + (size_t)(n + nOff) * K + k;
    Th[o] = hb; Tl[o] = lb;
}

/* combined Wqk|Wv split into the fused [2*DDIM][DDIM] layout */
__global__ void __launch_bounds__(256) wsplit_qkv_k(
    const float* __restrict__ Wqk, const float* __restrict__ Wv,
    __nv_bfloat16* __restrict__ Th, __nv_bfloat16* __restrict__ Tl)
{
    const int t1 = NDEPTH*DDIM*DDIM;
    int idx = blockIdx.x * 256 + threadIdx.x;
    if (idx >= 2*t1) return;
    const float* W = (idx < t1) ? Wqk : Wv;
    int nOff = (idx < t1) ? 0 : DDIM;
    int i = (idx < t1) ? idx : idx - t1;
    int kn = DDIM * DDIM;
    int l = i / kn, r = i - l * kn;
    int k = r / DDIM, n = r - k * DDIM;
    float w = W[i];
    __nv_bfloat16 hb, lb;
    split2(w, hb, lb);
    size_t o = (size_t)l * 2*DDIM*DDIM + (size_t)(n + nOff) * DDIM + k;
    Th[o] = hb; Tl[o] = lb;
}

/* -------------------------------------------------------------- layernorm  */
__global__ void __launch_bounds__(128) ln_k(
    const float* __restrict__ x, const float* __restrict__ xb,
    const float* __restrict__ g, const float* __restrict__ bta,
    float* __restrict__ outf,
    __nv_bfloat16* __restrict__ outh, __nv_bfloat16* __restrict__ outl)
{
    int warp = threadIdx.x >> 5, lane = threadIdx.x & 31;
    int row  = blockIdx.x * 4 + warp;
    int off  = row * DDIM + lane * 4;
    float4 a = *(const float4*)&x[off];
    if (xb) {
        float4 c = *(const float4*)&xb[off];
        a.x = (a.x + c.x) * 0.5f; a.y = (a.y + c.y) * 0.5f;
        a.z = (a.z + c.z) * 0.5f; a.w = (a.w + c.w) * 0.5f;
    }
    float s = a.x + a.y + a.z + a.w;
    #pragma unroll
    for (int o = 16; o; o >>= 1) s += __shfl_xor_sync(0xffffffffu, s, o);
    float mu = s * (1.0f/128.0f);
    float d0 = a.x-mu, d1 = a.y-mu, d2 = a.z-mu, d3 = a.w-mu;
    float q = d0*d0 + d1*d1 + d2*d2 + d3*d3;
    #pragma unroll
    for (int o = 16; o; o >>= 1) q += __shfl_xor_sync(0xffffffffu, q, o);
    float r = rsqrtf(q * (1.0f/128.0f) + 1e-5f);
    float4 gg = *(const float4*)&g[lane*4];
    float4 bb = *(const float4*)&bta[lane*4];
    float ov[4];
    ov[0] = d0*r*gg.x + bb.x;  ov[1] = d1*r*gg.y + bb.y;
    ov[2] = d2*r*gg.z + bb.z;  ov[3] = d3*r*gg.w + bb.w;
    if (outf) {
        *(float4*)&outf[off] = make_float4(ov[0], ov[1], ov[2], ov[3]);
    }
    if (outh) {
        union { __nv_bfloat16 b[4]; uint2 u; } ph, pl;
        #pragma unroll
        for (int j = 0; j < 4; j++) split2(ov[j], ph.b[j], pl.b[j]);
        *(uint2*)&outh[off] = ph.u;
        *(uint2*)&outl[off] = pl.u;
    }
}

/* ----------------------------------------------------- HMMA bf16x3 GEMM    */
/* C[M,Ntot] = A[M,K] @ B^T, B stored [Ntot][K] (hi/lo pairs).               */
/* CTA tile 128x128, 16 warps (4x4) of 32x32, K-chunks of 64.                */
/* cp.async 2-stage pipeline; smem: 2 stages x 4 tiles [128][64bf16]@144B.   */
#define TSTRIDE 144
#define TSIZE   (128*TSTRIDE)   /* 18432 */
#define STAGE   (4*TSIZE)       /* 73728 */
#define GSMEM   (2*STAGE)       /* 147456 */

__global__ void __launch_bounds__(512) mma_gemm_k(
    const __nv_bfloat16* __restrict__ Ah, const __nv_bfloat16* __restrict__ Al,
    const __nv_bfloat16* __restrict__ Bh, const __nv_bfloat16* __restrict__ Bl,
    int K, int Ntot,
    const float* __restrict__ bias, const float* __restrict__ res,
    float* __restrict__ Cf,
    __nv_bfloat16* __restrict__ Ch, __nv_bfloat16* __restrict__ Cl,
    int do_gelu)
{
    extern __shared__ char sm[];

    int tid = threadIdx.x;
    int lane = tid & 31, w = tid >> 5;
    int wr = (w >> 2) * 32;            /* warp row base in tile: 4 groups */
    int wc = (w & 3) * 32;             /* warp col base in tile: 4 groups */
    int rowBase = blockIdx.y * 128;
    int colBase = blockIdx.x * 128;
    int g  = lane >> 2, t4 = lane & 3;

    float acc[2][4][4];
    #pragma unroll
    for (int mi = 0; mi < 2; mi++)
        #pragma unroll
        for (int ni = 0; ni < 4; ni++)
            #pragma unroll
            for (int j = 0; j < 4; j++) acc[mi][ni][j] = 0.0f;

    int nchunks = K >> 6;
    /* per-thread fill coords: 2 chunks of 16B per tensor (512 thr x 2 = 1024) */
    int fr[2], fc[2];
    unsigned fso[2];
    #pragma unroll
    for (int t = 0; t < 2; t++) {
        int idx = tid + t * 512;
        fr[t] = idx >> 3;
        fc[t] = (idx & 7) * 8;
        fso[t] = fr[t] * TSTRIDE + fc[t] * 2;
    }

    auto issue = [&](int c, int st) {
        unsigned sb = smem_u32(sm + st * STAGE);
        int k0 = c << 6;
        #pragma unroll
        for (int t = 0; t < 2; t++) {
            size_t gA = (size_t)(rowBase + fr[t]) * K + k0 + fc[t];
            size_t gB = (size_t)(colBase + fr[t]) * K + k0 + fc[t];
            cpa16(sb + fso[t],             Ah + gA);
            cpa16(sb + TSIZE + fso[t],     Al + gA);
            cpa16(sb + 2*TSIZE + fso[t],   Bh + gB);
            cpa16(sb + 3*TSIZE + fso[t],   Bl + gB);
        }
        CP_COMMIT();
    };

    issue(0, 0);

    for (int c = 0; c < nchunks; c++) {
        if (c + 1 < nchunks) {
            issue(c + 1, (c + 1) & 1);
            CP_WAIT(1);
        } else {
            CP_WAIT(0);
        }
        __syncthreads();

        char* sAh = sm + (c & 1) * STAGE;
        char* sAl = sAh + TSIZE;
        char* sBh = sAh + 2*TSIZE;
        char* sBl = sAh + 3*TSIZE;

        #pragma unroll
        for (int kk = 0; kk < 4; kk++) {
            unsigned ah[2][4], al[2][4];
            #pragma unroll
            for (int mi = 0; mi < 2; mi++) {
                unsigned addr = smem_u32(sAh
                    + (wr + mi*16 + (lane & 15)) * TSTRIDE
                    + (kk*16 + (lane >> 4) * 8) * 2);
                ldmx4(ah[mi], addr);
                ldmx4(al[mi], addr + TSIZE);
            }
            #pragma unroll
            for (int ni = 0; ni < 4; ni++) {
                int n  = wc + ni*8 + g;
                int kb = (kk*16 + t4*2) * 2;
                unsigned bh0 = *(const unsigned*)(sBh + n*TSTRIDE + kb);
                unsigned bh1 = *(const unsigned*)(sBh + n*TSTRIDE + kb + 16);
                unsigned bl0 = *(const unsigned*)(sBl + n*TSTRIDE + kb);
                unsigned bl1 = *(const unsigned*)(sBl + n*TSTRIDE + kb + 16);
                #pragma unroll
                for (int mi = 0; mi < 2; mi++) {
                    mma_bf16(acc[mi][ni], ah[mi], bh0, bh1);
                    mma_bf16(acc[mi][ni], ah[mi], bl0, bl1);
                    mma_bf16(acc[mi][ni], al[mi], bh0, bh1);
                }
            }
        }
        __syncthreads();
    }

    /* epilogue */
    #pragma unroll
    for (int mi = 0; mi < 2; mi++) {
        #pragma unroll
        for (int ni = 0; ni < 4; ni++) {
            int col = colBase + wc + ni*8 + t4*2;
            float b0v = 0.f, b1v = 0.f;
            if (bias) { b0v = bias[col]; b1v = bias[col+1]; }
            #pragma unroll
            for (int half = 0; half < 2; half++) {
                int row = rowBase + wr + mi*16 + g + half*8;
                float v0 = acc[mi][ni][half*2+0] + b0v;
                float v1 = acc[mi][ni][half*2+1] + b1v;
                if (do_gelu) { v0 = gelu_f(v0); v1 = gelu_f(v1); }
                size_t co = (size_t)row * Ntot + col;
                if (res) {
                    float2 rv = *(const float2*)&res[co];
                    v0 += rv.x; v1 += rv.y;
                }
                if (Cf) *(float2*)&Cf[co] = make_float2(v0, v1);
                if (Ch) {
                    union { __nv_bfloat16 b[2]; unsigned u; } ph, pl;
                    split2(v0, ph.b[0], pl.b[0]);
                    split2(v1, ph.b[1], pl.b[1]);
                    *(unsigned*)&Ch[co] = ph.u;
                    *(unsigned*)&Cl[co] = pl.u;
                }
            }
        }
    }
}

/* --------------------------------------------------------------- attention */
/* qkv layout: [row][256], qk = cols 0..127, v = cols 128..255.              */
/* Max-free softmax: |scores| bounded (LN-bounded), self exp(-5e4) == 0.     */
__global__ void __launch_bounds__(384) attn_k(
    const float* __restrict__ qkv,
    __nv_bfloat16* __restrict__ oh, __nv_bfloat16* __restrict__ ol)
{
    __shared__ float ks[LL][DHH];
    __shared__ float vs[LL][DHH];
    int bh = blockIdx.x;
    int b  = bh >> 3, h = bh & 7;
    int tid = threadIdx.x;
    const float* qbase = qkv + (size_t)(b*LL)*256 + h*DHH;
    const float* vbase = qbase + DDIM;

    for (int i = tid; i < LL*4; i += 384) {
        int row = i >> 2, q4 = (i & 3) * 4;
        *(float4*)&ks[row][q4] = *(const float4*)&qbase[(size_t)row*256 + q4];
        *(float4*)&vs[row][q4] = *(const float4*)&vbase[(size_t)row*256 + q4];
    }
    __syncthreads();

    int i = tid;
    float q[DHH];
    #pragma unroll
    for (int d = 0; d < DHH; d++) q[d] = ks[i][d];
    float nrm = 0.f;
    #pragma unroll
    for (int d = 0; d < DHH; d++) nrm += q[d]*q[d];
    nrm = fmaxf(sqrtf(nrm), 1e-12f);
    float inv = 1.0f / nrm;
    #pragma unroll
    for (int d = 0; d < DHH; d++) ks[i][d] = q[d] * inv;
    __syncthreads();

    float s = 0.0f;
    float acc[DHH];
    #pragma unroll
    for (int d = 0; d < DHH; d++) acc[d] = 0.0f;
    const float scale = 0.25f;
    for (int j = 0; j < i; j++) {
        float dot = 0.f;
        #pragma unroll
        for (int d = 0; d < DHH; d++) dot += q[d] * ks[j][d];
        float p = __expf(dot * scale);
        s += p;
        #pragma unroll
        for (int d = 0; d < DHH; d++) acc[d] += p * vs[j][d];
    }
    float invs;
    if (i == 0) {
        invs = 1.0f;
        #pragma unroll
        for (int d = 0; d < DHH; d++) acc[d] = vs[0][d];
    } else {
        invs = 1.0f / s;
    }
    size_t ob = (size_t)(b*LL + i)*DDIM + h*DHH;
    #pragma unroll
    for (int d = 0; d < DHH; d += 4) {
        union { __nv_bfloat16 b[4]; uint2 u; } ph, pl;
        split2(acc[d+0]*invs, ph.b[0], pl.b[0]);
        split2(acc[d+1]*invs, ph.b[1], pl.b[1]);
        split2(acc[d+2]*invs, ph.b[2], pl.b[2]);
        split2(acc[d+3]*invs, ph.b[3], pl.b[3]);
        *(uint2*)&oh[ob + d] = ph.u;
        *(uint2*)&ol[ob + d] = pl.u;
    }
}

/* --------------------------------------------- final projection (split-K)  */
__global__ void __launch_bounds__(256) proj_partial_k(
    const float* __restrict__ xf, const float* __restrict__ Wp,
    float* __restrict__ part)
{
    __shared__ float xs[64][133];
    __shared__ float ws[128][17];
    int cg = blockIdx.x;
    int sp = blockIdx.y;
    int tb = threadIdx.x & 63;
    int tc = (threadIdx.x >> 6) << 2;
    float a0=0,a1=0,a2=0,a3=0;
    for (int kc = 0; kc < KSPLIT; kc += 128) {
        int k0 = sp*KSPLIT + kc;
        for (int i = threadIdx.x; i < 2048; i += 256) {
            int bb2 = i >> 5; int q4 = (i & 31) << 2;
            float4 vv = *(const float4*)&xf[(size_t)bb2*KP + k0 + q4];
            xs[bb2][q4] = vv.x; xs[bb2][q4+1] = vv.y;
            xs[bb2][q4+2] = vv.z; xs[bb2][q4+3] = vv.w;
        }
        for (int i = threadIdx.x; i < 512; i += 256) {
            int kk = i >> 2; int c4 = (i & 3) << 2;
            float4 vv = *(const float4*)&Wp[(size_t)(k0+kk)*128 + cg*16 + c4];
            ws[kk][c4] = vv.x; ws[kk][c4+1] = vv.y;
            ws[kk][c4+2] = vv.z; ws[kk][c4+3] = vv.w;
        }
        __syncthreads();
        #pragma unroll 8
        for (int kk = 0; kk < 128; kk++) {
            float xv = xs[tb][kk];
            a0 += xv * ws[kk][tc+0];
            a1 += xv * ws[kk][tc+1];
            a2 += xv * ws[kk][tc+2];
            a3 += xv * ws[kk][tc+3];
        }
        __syncthreads();
    }
    int base = sp*(BB*128) + tb*128 + cg*16 + tc;
    part[base+0]=a0; part[base+1]=a1; part[base+2]=a2; part[base+3]=a3;
}

__global__ void __launch_bounds__(256) proj_reduce_k(
    const float* __restrict__ part, const float* __restrict__ bp,
    float* __restrict__ out)
{
    int idx = blockIdx.x * 256 + threadIdx.x;
    float s = bp[idx & 127];
    #pragma unroll
    for (int sp = 0; sp < NSPLIT; sp++) s += part[sp*(BB*128) + idx];
    out[idx] = s;
}

/* ------------------------------------------------------------------ driver */
extern "C" void kernel_launch(void* const* d_in, const int* in_sizes, int n_in,
                              void* d_out, int out_size)
{
    (void)in_sizes; (void)n_in; (void)out_size;
    const int*   x_enc = (const int*)  d_in[0];
    const float* emb   = (const float*)d_in[1];
    const float* pos1  = (const float*)d_in[2];
    const float* pos2  = (const float*)d_in[3];
    const float* ln1_g = (const float*)d_in[4];
    const float* ln1_b = (const float*)d_in[5];
    const float* Wqk   = (const float*)d_in[6];
    const float* Wv    = (const float*)d_in[7];
    const float* Wo    = (const float*)d_in[8];
    const float* bo    = (const float*)d_in[9];
    const float* ln2_g = (const float*)d_in[10];
    const float* ln2_b = (const float*)d_in[11];
    const float* W1    = (const float*)d_in[12];
    const float* b1    = (const float*)d_in[13];
    const float* W2    = (const float*)d_in[14];
    const float* b2    = (const float*)d_in[15];
    const float* lnf_g = (const float*)d_in[16];
    const float* lnf_b = (const float*)d_in[17];
    const float* Wp    = (const float*)d_in[18];
    const float* bp    = (const float*)d_in[19];

    float *x1,*x2,*h,*qkv,*part;
    cudaGetSymbolAddress((void**)&x1,  g_x1);
    cudaGetSymbolAddress((void**)&x2,  g_x2);
    cudaGetSymbolAddress((void**)&h,   g_h);
    cudaGetSymbolAddress((void**)&qkv, g_qkv);
    cudaGetSymbolAddress((void**)&part,g_part);

    __nv_bfloat16 *hh,*hl,*oh,*ol,*ah,*al;
    __nv_bfloat16 *wqvh,*wqvl,*woh,*wol,*w1h,*w1l,*w2h,*w2l;
    cudaGetSymbolAddress((void**)&hh, g_hh);   cudaGetSymbolAddress((void**)&hl, g_hl);
    cudaGetSymbolAddress((void**)&oh, g_oh);   cudaGetSymbolAddress((void**)&ol, g_ol);
    cudaGetSymbolAddress((void**)&ah, g_ah);   cudaGetSymbolAddress((void**)&al, g_al);
    cudaGetSymbolAddress((void**)&wqvh, g_wqvh); cudaGetSymbolAddress((void**)&wqvl, g_wqvl);
    cudaGetSymbolAddress((void**)&woh,  g_woh);  cudaGetSymbolAddress((void**)&wol,  g_wol);
    cudaGetSymbolAddress((void**)&w1h,  g_w1h);  cudaGetSymbolAddress((void**)&w1l,  g_w1l);
    cudaGetSymbolAddress((void**)&w2h,  g_w2h);  cudaGetSymbolAddress((void**)&w2l,  g_w2l);

    cudaFuncSetAttribute(mma_gemm_k, cudaFuncAttributeMaxDynamicSharedMemorySize, GSMEM);

    int t1 = NDEPTH*DDIM*DDIM;
    int t2 = NDEPTH*DDIM*FFD;

    dim3 gD(1, BLD/128);   /* Ntot=128 */
    dim3 gQ(2, BLD/128);   /* Ntot=256 (fused qkv) */
    dim3 gF(4, BLD/128);   /* Ntot=512 */

    /* launch order puts the first mma_gemm_k at launch #4 (ncu captures #4) */
    embed_k<<<(BLD*DDIM)/256, 256>>>(x_enc, emb, pos1, pos2, x1, x2);               /* 1 */
    ln_k<<<BLD/4, 128>>>(x2, nullptr, ln1_g, ln1_b, nullptr, hh, hl);               /* 2 */
    wsplit_qkv_k<<<(2*t1+255)/256, 256>>>(Wqk, Wv, wqvh, wqvl);                     /* 3 */
    mma_gemm_k<<<gQ, 512, GSMEM>>>(hh, hl, wqvh, wqvl,                              /* 4 */
                                   DDIM, 2*DDIM, nullptr, nullptr, qkv,
                                   nullptr, nullptr, 0);
    wsplit_k<<<(t1+255)/256, 256>>>(Wo,  woh,  wol,  DDIM, DDIM, 0, DDIM, t1);      /* 5 */
    wsplit_k<<<(t2+255)/256, 256>>>(W1,  w1h,  w1l,  DDIM, FFD,  0, FFD,  t2);      /* 6 */
    wsplit_k<<<(t2+255)/256, 256>>>(W2,  w2h,  w2l,  FFD,  DDIM, 0, DDIM, t2);      /* 7 */

    for (int d = 0; d < NDEPTH; d++) {
        size_t wsq = (size_t)d*DDIM*DDIM;
        if (d > 0) {
            ln_k<<<BLD/4, 128>>>(x2, nullptr, ln1_g + d*DDIM, ln1_b + d*DDIM,
                                 nullptr, hh, hl);
            mma_gemm_k<<<gQ, 512, GSMEM>>>(hh, hl,
                                           wqvh + (size_t)d*2*DDIM*DDIM,
                                           wqvl + (size_t)d*2*DDIM*DDIM,
                                           DDIM, 2*DDIM, nullptr, nullptr, qkv,
                                           nullptr, nullptr, 0);
        }
        attn_k<<<BB*HH, 384>>>(qkv, oh, ol);
        /* x1 = x1 + o@Wo + bo */
        mma_gemm_k<<<gD, 512, GSMEM>>>(oh, ol, woh + wsq, wol + wsq,
                                       DDIM, DDIM, bo + d*DDIM, x1, x1,
                                       nullptr, nullptr, 0);
        ln_k<<<BLD/4, 128>>>(x1, nullptr, ln2_g + d*DDIM, ln2_b + d*DDIM,
                             nullptr, hh, hl);
        /* a = gelu(h@W1 + b1) -> split */
        mma_gemm_k<<<gF, 512, GSMEM>>>(hh, hl,
                                       w1h + (size_t)d*DDIM*FFD, w1l + (size_t)d*DDIM*FFD,
                                       DDIM, FFD, b1 + d*FFD, nullptr, nullptr,
                                       ah, al, 1);
        /* x2 = x2 + a@W2 + b2 */
        mma_gemm_k<<<gD, 512, GSMEM>>>(ah, al,
                                       w2h + (size_t)d*FFD*DDIM, w2l + (size_t)d*FFD*DDIM,
                                       FFD, DDIM, b2 + d*DDIM, x2, x2,
                                       nullptr, nullptr, 0);
    }

    ln_k<<<BLD/4, 128>>>(x1, x2, lnf_g, lnf_b, h, nullptr, nullptr);
    dim3 gp(8, NSPLIT);
    proj_partial_k<<<gp, 256>>>(h, Wp, part);
    proj_reduce_k<<<NSPLIT, 256>>>(part, bp, (float*)d_out);
}

// round 13
// speedup vs baseline: 1.5742x; 1.0250x over previous
#include <cuda_runtime.h>
#include <cuda_bf16.h>
#include <stdint.h>
#include <math.h>

#define BB   64
#define LL   384
#define DDIM 128
#define HH   8
#define DHH  16
#define NDEPTH 6
#define FFD  512
#define BLD  (BB*LL)          /* 24576 rows */
#define KP   (LL*DDIM)        /* 49152     */
#define NSPLIT 32
#define KSPLIT (KP/NSPLIT)    /* 1536 */

/* ------------------------------------------------------------------ scratch */
__device__ float g_x1[BLD*DDIM];
__device__ float g_x2[BLD*DDIM];
__device__ float g_h [BLD*DDIM];          /* fp32 (final LN -> proj) */
__device__ float g_qkv[BLD*2*DDIM];       /* fused qk|v output [row][256] */
__device__ float g_part[NSPLIT*BB*128];

/* bf16 operands: panel layout [np][rows][128], swizzled within rows; 16B-aligned for bulk */
__device__ __align__(256) __nv_bfloat16 g_hh[BLD*DDIM];
__device__ __align__(256) __nv_bfloat16 g_hl[BLD*DDIM];
__device__ __align__(256) __nv_bfloat16 g_oh[BLD*DDIM];
__device__ __align__(256) __nv_bfloat16 g_ol[BLD*DDIM];
__device__ __align__(256) __nv_bfloat16 g_ah[BLD*FFD];   /* 4 panels */
__device__ __align__(256) __nv_bfloat16 g_al[BLD*FFD];

/* transposed + split weights: [layer][np][N][128] */
__device__ __align__(256) __nv_bfloat16 g_wqvh[NDEPTH*2*DDIM*DDIM], g_wqvl[NDEPTH*2*DDIM*DDIM];
__device__ __align__(256) __nv_bfloat16 g_woh [NDEPTH*DDIM*DDIM],   g_wol [NDEPTH*DDIM*DDIM];
__device__ __align__(256) __nv_bfloat16 g_w1h [NDEPTH*DDIM*FFD],    g_w1l [NDEPTH*DDIM*FFD];
__device__ __align__(256) __nv_bfloat16 g_w2h [NDEPTH*FFD*DDIM],    g_w2l [NDEPTH*FFD*DDIM];

/* ------------------------------------------------------------ helpers      */
__device__ __forceinline__ unsigned smem_u32(const void* p) {
    unsigned a;
    asm("{ .reg .u64 t; cvta.to.shared.u64 t, %1; cvt.u32.u64 %0, t; }"
        : "=r"(a) : "l"(p));
    return a;
}
__device__ __forceinline__ void ldmx4(unsigned* r, unsigned addr) {
    asm volatile("ldmatrix.sync.aligned.m8n8.x4.shared.b16 {%0,%1,%2,%3}, [%4];"
        : "=r"(r[0]), "=r"(r[1]), "=r"(r[2]), "=r"(r[3]) : "r"(addr));
}
__device__ __forceinline__ void mma_bf16(float* c, const unsigned* a,
                                         unsigned b0, unsigned b1) {
    asm volatile("mma.sync.aligned.m16n8k16.row.col.f32.bf16.bf16.f32 "
        "{%0,%1,%2,%3}, {%4,%5,%6,%7}, {%8,%9}, {%0,%1,%2,%3};"
        : "+f"(c[0]), "+f"(c[1]), "+f"(c[2]), "+f"(c[3])
        : "r"(a[0]), "r"(a[1]), "r"(a[2]), "r"(a[3]), "r"(b0), "r"(b1));
}
__device__ __forceinline__ void bulk_cp(unsigned dst, const void* src,
                                        unsigned bytes, unsigned mbar) {
    asm volatile(
        "cp.async.bulk.shared::cluster.global.mbarrier::complete_tx::bytes "
        "[%0], [%1], %2, [%3];"
        :: "r"(dst), "l"(src), "r"(bytes), "r"(mbar) : "memory");
}
#define MBAR_INIT(mb, c)  asm volatile("mbarrier.init.shared.b64 [%0], %1;" :: "r"(mb), "r"((unsigned)(c)) : "memory")
#define MBAR_EXPECT(mb,n) asm volatile("mbarrier.arrive.expect_tx.shared.b64 _, [%0], %1;" :: "r"(mb), "r"((unsigned)(n)) : "memory")

__device__ __forceinline__ void mbar_wait(unsigned mb, unsigned parity) {
    unsigned done;
    asm volatile("{ .reg .pred p; mbarrier.try_wait.parity.acquire.cta.shared::cta.b64 p, [%1], %2; selp.b32 %0,1,0,p; }"
                 : "=r"(done) : "r"(mb), "r"(parity) : "memory");
    if (!done) {
        asm volatile("{ .reg .pred P1; WL_%=: mbarrier.try_wait.parity.acquire.cta.shared::cta.b64 P1, [%0], %1, 0x989680; @P1 bra.uni WD_%=; bra.uni WL_%=; WD_%=: }"
                     :: "r"(mb), "r"(parity) : "memory");
    }
}

__device__ __forceinline__ float gelu_f(float x) {
    return 0.5f * x * (1.0f + erff(x * 0.70710678118654752f));
}
__device__ __forceinline__ void split2(float x, __nv_bfloat16& h, __nv_bfloat16& l) {
    h = __float2bfloat16(x);
    l = __float2bfloat16(x - __bfloat162float(h));
}
/* swizzled element offset within a [row][128] panel row (chunk ^= row&15) */
__device__ __forceinline__ int swoff(int row, int col) {
    return ((((col >> 3) ^ (row & 15)) << 3) | (col & 7));
}

/* --------------------------------------------------------------- embedding */
__global__ void __launch_bounds__(256) embed_k(
    const int* __restrict__ x_enc, const float* __restrict__ emb,
    const float* __restrict__ pos1, const float* __restrict__ pos2,
    float* __restrict__ x1, float* __restrict__ x2)
{
    int idx = blockIdx.x * 256 + threadIdx.x;
    if (idx >= BLD*DDIM) return;
    int d   = idx & (DDIM-1);
    int bl  = idx >> 7;
    int l   = bl % LL;
    int tok = x_enc[bl];
    float v = emb[(size_t)tok*DDIM + d] + pos1[(l/25)*DDIM + d] + pos2[(l%25)*DDIM + d];
    x1[idx] = v;
    x2[idx] = v;
}

/* ---------------------------------------------------- weight split+transp. */
/* W: [L][K][N] fp32 -> Th/Tl: [L][np][N][128] bf16 swizzled (np = K/128)   */
__global__ void __launch_bounds__(256) wsplit_k(
    const float* __restrict__ W, __nv_bfloat16* __restrict__ Th,
    __nv_bfloat16* __restrict__ Tl, int K, int N, int nOff, int nTot, int total)
{
    int idx = blockIdx.x * 256 + threadIdx.x;
    if (idx >= total) return;
    int np = K >> 7;
    int kn = K * N;
    int l = idx / kn, r = idx - l * kn;
    int k = r / N, n = r - k * N;
    float w = W[idx];
    __nv_bfloat16 hb, lb;
    split2(w, hb, lb);
    int p = k >> 7, kc = k & 127;
    int nn = n + nOff;
    size_t o = (((size_t)l * np + p) * nTot + nn) * 128 + swoff(nn, kc);
    Th[o] = hb; Tl[o] = lb;
}

/* combined Wqk|Wv split into the fused [256][128] layout (K=128, np=1) */
__global__ void __launch_bounds__(256) wsplit_qkv_k(
    const float* __restrict__ Wqk, const float* __restrict__ Wv,
    __nv_bfloat16* __restrict__ Th, __nv_bfloat16* __restrict__ Tl)
{
    const int t1 = NDEPTH*DDIM*DDIM;
    int idx = blockIdx.x * 256 + threadIdx.x;
    if (idx >= 2*t1) return;
    const float* W = (idx < t1) ? Wqk : Wv;
    int nOff = (idx < t1) ? 0 : DDIM;
    int i = (idx < t1) ? idx : idx - t1;
    int kn = DDIM * DDIM;
    int l = i / kn, r = i - l * kn;
    int k = r / DDIM, n = r - k * DDIM;
    float w = W[i];
    __nv_bfloat16 hb, lb;
    split2(w, hb, lb);
    int nn = n + nOff;
    size_t o = ((size_t)l * 2*DDIM + nn) * 128 + swoff(nn, k);
    Th[o] = hb; Tl[o] = lb;
}

/* -------------------------------------------------------------- layernorm  */
__global__ void __launch_bounds__(128) ln_k(
    const float* __restrict__ x, const float* __restrict__ xb,
    const float* __restrict__ g, const float* __restrict__ bta,
    float* __restrict__ outf,
    __nv_bfloat16* __restrict__ outh, __nv_bfloat16* __restrict__ outl)
{
    int warp = threadIdx.x >> 5, lane = threadIdx.x & 31;
    int row  = blockIdx.x * 4 + warp;
    int off  = row * DDIM + lane * 4;
    float4 a = *(const float4*)&x[off];
    if (xb) {
        float4 c = *(const float4*)&xb[off];
        a.x = (a.x + c.x) * 0.5f; a.y = (a.y + c.y) * 0.5f;
        a.z = (a.z + c.z) * 0.5f; a.w = (a.w + c.w) * 0.5f;
    }
    float s = a.x + a.y + a.z + a.w;
    #pragma unroll
    for (int o = 16; o; o >>= 1) s += __shfl_xor_sync(0xffffffffu, s, o);
    float mu = s * (1.0f/128.0f);
    float d0 = a.x-mu, d1 = a.y-mu, d2 = a.z-mu, d3 = a.w-mu;
    float q = d0*d0 + d1*d1 + d2*d2 + d3*d3;
    #pragma unroll
    for (int o = 16; o; o >>= 1) q += __shfl_xor_sync(0xffffffffu, q, o);
    float r = rsqrtf(q * (1.0f/128.0f) + 1e-5f);
    float4 gg = *(const float4*)&g[lane*4];
    float4 bb = *(const float4*)&bta[lane*4];
    float ov[4];
    ov[0] = d0*r*gg.x + bb.x;  ov[1] = d1*r*gg.y + bb.y;
    ov[2] = d2*r*gg.z + bb.z;  ov[3] = d3*r*gg.w + bb.w;
    if (outf) {
        *(float4*)&outf[off] = make_float4(ov[0], ov[1], ov[2], ov[3]);
    }
    if (outh) {
        union { __nv_bfloat16 b[4]; uint2 u; } ph, pl;
        #pragma unroll
        for (int j = 0; j < 4; j++) split2(ov[j], ph.b[j], pl.b[j]);
        size_t so = (size_t)row * 128 + swoff(row, lane * 4);
        *(uint2*)&outh[so] = ph.u;
        *(uint2*)&outl[so] = pl.u;
    }
}

/* ------------------------------------------- bulk-load HMMA bf16x3 GEMM    */
/* C[M,Ntot] = A[M,K] @ B^T.  A: [np][BLD][128] swizzled; B: [np][Ntot][128]*/
/* CTA tile 128x128, 16 warps (4x4) of 32x32; per panel: 4x 32KB bulk copies*/
#define PTILE  32768
#define PGSMEM (4*PTILE)   /* 131072 */

__global__ void __launch_bounds__(512) blk_gemm_k(
    const __nv_bfloat16* __restrict__ Ah, const __nv_bfloat16* __restrict__ Al,
    const __nv_bfloat16* __restrict__ Bh, const __nv_bfloat16* __restrict__ Bl,
    int np, int Ntot,
    const float* __restrict__ bias, const float* __restrict__ res,
    float* __restrict__ Cf,
    __nv_bfloat16* __restrict__ Ch, __nv_bfloat16* __restrict__ Cl,
    int do_gelu)
{
    extern __shared__ char sm[];
    __shared__ __align__(8) unsigned long long s_bar;

    char* sAh = sm;
    char* sAl = sm + PTILE;
    char* sBh = sm + 2*PTILE;
    char* sBl = sm + 3*PTILE;

    int tid = threadIdx.x;
    int lane = tid & 31, w = tid >> 5;
    int wr = (w >> 2) * 32;
    int wc = (w & 3) * 32;
    int rowBase = blockIdx.y * 128;
    int colBase = blockIdx.x * 128;
    int g  = lane >> 2, t4 = lane & 3;

    unsigned mb = smem_u32(&s_bar);
    if (tid == 0) MBAR_INIT(mb, 1);
    __syncthreads();

    float acc[2][4][4];
    #pragma unroll
    for (int mi = 0; mi < 2; mi++)
        #pragma unroll
        for (int ni = 0; ni < 4; ni++)
            #pragma unroll
            for (int j = 0; j < 4; j++) acc[mi][ni][j] = 0.0f;

    unsigned sA = smem_u32(sAh);
    unsigned sB = smem_u32(sBh);

    for (int p = 0; p < np; p++) {
        if (tid == 0) {
            MBAR_EXPECT(mb, PGSMEM);
            size_t ao = ((size_t)p * BLD  + rowBase) * 128;
            size_t bo = ((size_t)p * Ntot + colBase) * 128;
            bulk_cp(sA,           Ah + ao, PTILE, mb);
            bulk_cp(sA + PTILE,   Al + ao, PTILE, mb);
            bulk_cp(sB,           Bh + bo, PTILE, mb);
            bulk_cp(sB + PTILE,   Bl + bo, PTILE, mb);
        }
        mbar_wait(mb, (unsigned)(p & 1));

        #pragma unroll
        for (int kk = 0; kk < 8; kk++) {
            unsigned ah[2][4], al[2][4];
            #pragma unroll
            for (int mi = 0; mi < 2; mi++) {
                int rl = wr + mi*16 + (lane & 15);
                int chunk = kk*2 + (lane >> 4);
                unsigned addr = sA + rl*256 + (((unsigned)(chunk ^ (rl & 15))) << 4);
                ldmx4(ah[mi], addr);
                ldmx4(al[mi], addr + PTILE);
            }
            #pragma unroll
            for (int ni = 0; ni < 4; ni++) {
                int n  = wc + ni*8 + g;
                int c0 = (kk*2)     ^ (n & 15);
                int c1 = (kk*2 + 1) ^ (n & 15);
                unsigned b0a = n*256 + (c0 << 4) + t4*4;
                unsigned b1a = n*256 + (c1 << 4) + t4*4;
                unsigned bh0 = *(const unsigned*)(sBh + b0a);
                unsigned bh1 = *(const unsigned*)(sBh + b1a);
                unsigned bl0 = *(const unsigned*)(sBl + b0a);
                unsigned bl1 = *(const unsigned*)(sBl + b1a);
                #pragma unroll
                for (int mi = 0; mi < 2; mi++) {
                    mma_bf16(acc[mi][ni], ah[mi], bh0, bh1);
                    mma_bf16(acc[mi][ni], ah[mi], bl0, bl1);
                    mma_bf16(acc[mi][ni], al[mi], bh0, bh1);
                }
            }
        }
        __syncthreads();   /* all reads done before next panel's bulk overwrite */
    }

    /* epilogue */
    #pragma unroll
    for (int mi = 0; mi < 2; mi++) {
        #pragma unroll
        for (int ni = 0; ni < 4; ni++) {
            int col = colBase + wc + ni*8 + t4*2;
            float b0v = 0.f, b1v = 0.f;
            if (bias) { b0v = bias[col]; b1v = bias[col+1]; }
            #pragma unroll
            for (int half = 0; half < 2; half++) {
                int row = rowBase + wr + mi*16 + g + half*8;
                float v0 = acc[mi][ni][half*2+0] + b0v;
                float v1 = acc[mi][ni][half*2+1] + b1v;
                if (do_gelu) { v0 = gelu_f(v0); v1 = gelu_f(v1); }
                size_t co = (size_t)row * Ntot + col;
                if (res) {
                    float2 rv = *(const float2*)&res[co];
                    v0 += rv.x; v1 += rv.y;
                }
                if (Cf) *(float2*)&Cf[co] = make_float2(v0, v1);
                if (Ch) {
                    union { __nv_bfloat16 b[2]; unsigned u; } ph, pl;
                    split2(v0, ph.b[0], pl.b[0]);
                    split2(v1, ph.b[1], pl.b[1]);
                    /* panel + swizzle layout for next-GEMM A operand */
                    size_t so = ((size_t)(col >> 7) * BLD + row) * 128
                              + swoff(row, col & 127);
                    *(unsigned*)&Ch[so] = ph.u;
                    *(unsigned*)&Cl[so] = pl.u;
                }
            }
        }
    }
}

/* --------------------------------------------------------------- attention */
/* qkv layout: [row][256], qk = cols 0..127, v = cols 128..255.              */
__global__ void __launch_bounds__(384) attn_k(
    const float* __restrict__ qkv,
    __nv_bfloat16* __restrict__ oh, __nv_bfloat16* __restrict__ ol)
{
    __shared__ float ks[LL][DHH];
    __shared__ float vs[LL][DHH];
    int bh = blockIdx.x;
    int b  = bh >> 3, h = bh & 7;
    int tid = threadIdx.x;
    const float* qbase = qkv + (size_t)(b*LL)*256 + h*DHH;
    const float* vbase = qbase + DDIM;

    for (int i = tid; i < LL*4; i += 384) {
        int row = i >> 2, q4 = (i & 3) * 4;
        *(float4*)&ks[row][q4] = *(const float4*)&qbase[(size_t)row*256 + q4];
        *(float4*)&vs[row][q4] = *(const float4*)&vbase[(size_t)row*256 + q4];
    }
    __syncthreads();

    int i = tid;
    float q[DHH];
    #pragma unroll
    for (int d = 0; d < DHH; d++) q[d] = ks[i][d];
    float nrm = 0.f;
    #pragma unroll
    for (int d = 0; d < DHH; d++) nrm += q[d]*q[d];
    nrm = fmaxf(sqrtf(nrm), 1e-12f);
    float inv = 1.0f / nrm;
    #pragma unroll
    for (int d = 0; d < DHH; d++) ks[i][d] = q[d] * inv;
    __syncthreads();

    float s = 0.0f;
    float acc[DHH];
    #pragma unroll
    for (int d = 0; d < DHH; d++) acc[d] = 0.0f;
    const float scale = 0.25f;
    for (int j = 0; j < i; j++) {
        float dot = 0.f;
        #pragma unroll
        for (int d = 0; d < DHH; d++) dot += q[d] * ks[j][d];
        float p = __expf(dot * scale);
        s += p;
        #pragma unroll
        for (int d = 0; d < DHH; d++) acc[d] += p * vs[j][d];
    }
    float invs;
    if (i == 0) {
        invs = 1.0f;
        #pragma unroll
        for (int d = 0; d < DHH; d++) acc[d] = vs[0][d];
    } else {
        invs = 1.0f / s;
    }
    int row = b*LL + i;
    #pragma unroll
    for (int d = 0; d < DHH; d += 4) {
        union { __nv_bfloat16 b[4]; uint2 u; } ph, pl;
        split2(acc[d+0]*invs, ph.b[0], pl.b[0]);
        split2(acc[d+1]*invs, ph.b[1], pl.b[1]);
        split2(acc[d+2]*invs, ph.b[2], pl.b[2]);
        split2(acc[d+3]*invs, ph.b[3], pl.b[3]);
        size_t so = (size_t)row * 128 + swoff(row, h*DHH + d);
        *(uint2*)&oh[so] = ph.u;
        *(uint2*)&ol[so] = pl.u;
    }
}

/* --------------------------------------------- final projection (split-K)  */
__global__ void __launch_bounds__(256) proj_partial_k(
    const float* __restrict__ xf, const float* __restrict__ Wp,
    float* __restrict__ part)
{
    __shared__ float xs[64][133];
    __shared__ float ws[128][17];
    int cg = blockIdx.x;
    int sp = blockIdx.y;
    int tb = threadIdx.x & 63;
    int tc = (threadIdx.x >> 6) << 2;
    float a0=0,a1=0,a2=0,a3=0;
    for (int kc = 0; kc < KSPLIT; kc += 128) {
        int k0 = sp*KSPLIT + kc;
        for (int i = threadIdx.x; i < 2048; i += 256) {
            int bb2 = i >> 5; int q4 = (i & 31) << 2;
            float4 vv = *(const float4*)&xf[(size_t)bb2*KP + k0 + q4];
            xs[bb2][q4] = vv.x; xs[bb2][q4+1] = vv.y;
            xs[bb2][q4+2] = vv.z; xs[bb2][q4+3] = vv.w;
        }
        for (int i = threadIdx.x; i < 512; i += 256) {
            int kk = i >> 2; int c4 = (i & 3) << 2;
            float4 vv = *(const float4*)&Wp[(size_t)(k0+kk)*128 + cg*16 + c4];
            ws[kk][c4] = vv.x; ws[kk][c4+1] = vv.y;
            ws[kk][c4+2] = vv.z; ws[kk][c4+3] = vv.w;
        }
        __syncthreads();
        #pragma unroll 8
        for (int kk = 0; kk < 128; kk++) {
            float xv = xs[tb][kk];
            a0 += xv * ws[kk][tc+0];
            a1 += xv * ws[kk][tc+1];
            a2 += xv * ws[kk][tc+2];
            a3 += xv * ws[kk][tc+3];
        }
        __syncthreads();
    }
    int base = sp*(BB*128) + tb*128 + cg*16 + tc;
    part[base+0]=a0; part[base+1]=a1; part[base+2]=a2; part[base+3]=a3;
}

__global__ void __launch_bounds__(256) proj_reduce_k(
    const float* __restrict__ part, const float* __restrict__ bp,
    float* __restrict__ out)
{
    int idx = blockIdx.x * 256 + threadIdx.x;
    float s = bp[idx & 127];
    #pragma unroll
    for (int sp = 0; sp < NSPLIT; sp++) s += part[sp*(BB*128) + idx];
    out[idx] = s;
}

/* ------------------------------------------------------------------ driver */
extern "C" void kernel_launch(void* const* d_in, const int* in_sizes, int n_in,
                              void* d_out, int out_size)
{
    (void)in_sizes; (void)n_in; (void)out_size;
    const int*   x_enc = (const int*)  d_in[0];
    const float* emb   = (const float*)d_in[1];
    const float* pos1  = (const float*)d_in[2];
    const float* pos2  = (const float*)d_in[3];
    const float* ln1_g = (const float*)d_in[4];
    const float* ln1_b = (const float*)d_in[5];
    const float* Wqk   = (const float*)d_in[6];
    const float* Wv    = (const float*)d_in[7];
    const float* Wo    = (const float*)d_in[8];
    const float* bo    = (const float*)d_in[9];
    const float* ln2_g = (const float*)d_in[10];
    const float* ln2_b = (const float*)d_in[11];
    const float* W1    = (const float*)d_in[12];
    const float* b1    = (const float*)d_in[13];
    const float* W2    = (const float*)d_in[14];
    const float* b2    = (const float*)d_in[15];
    const float* lnf_g = (const float*)d_in[16];
    const float* lnf_b = (const float*)d_in[17];
    const float* Wp    = (const float*)d_in[18];
    const float* bp    = (const float*)d_in[19];

    float *x1,*x2,*h,*qkv,*part;
    cudaGetSymbolAddress((void**)&x1,  g_x1);
    cudaGetSymbolAddress((void**)&x2,  g_x2);
    cudaGetSymbolAddress((void**)&h,   g_h);
    cudaGetSymbolAddress((void**)&qkv, g_qkv);
    cudaGetSymbolAddress((void**)&part,g_part);

    __nv_bfloat16 *hh,*hl,*oh,*ol,*ah,*al;
    __nv_bfloat16 *wqvh,*wqvl,*woh,*wol,*w1h,*w1l,*w2h,*w2l;
    cudaGetSymbolAddress((void**)&hh, g_hh);   cudaGetSymbolAddress((void**)&hl, g_hl);
    cudaGetSymbolAddress((void**)&oh, g_oh);   cudaGetSymbolAddress((void**)&ol, g_ol);
    cudaGetSymbolAddress((void**)&ah, g_ah);   cudaGetSymbolAddress((void**)&al, g_al);
    cudaGetSymbolAddress((void**)&wqvh, g_wqvh); cudaGetSymbolAddress((void**)&wqvl, g_wqvl);
    cudaGetSymbolAddress((void**)&woh,  g_woh);  cudaGetSymbolAddress((void**)&wol,  g_wol);
    cudaGetSymbolAddress((void**)&w1h,  g_w1h);  cudaGetSymbolAddress((void**)&w1l,  g_w1l);
    cudaGetSymbolAddress((void**)&w2h,  g_w2h);  cudaGetSymbolAddress((void**)&w2l,  g_w2l);

    cudaFuncSetAttribute(blk_gemm_k, cudaFuncAttributeMaxDynamicSharedMemorySize, PGSMEM);

    int t1 = NDEPTH*DDIM*DDIM;
    int t2 = NDEPTH*DDIM*FFD;

    dim3 gD(1, BLD/128);   /* Ntot=128 */
    dim3 gQ(2, BLD/128);   /* Ntot=256 (fused qkv) */
    dim3 gF(4, BLD/128);   /* Ntot=512 */

    /* launch order puts the first blk_gemm_k at launch #4 (ncu captures #4) */
    embed_k<<<(BLD*DDIM)/256, 256>>>(x_enc, emb, pos1, pos2, x1, x2);               /* 1 */
    ln_k<<<BLD/4, 128>>>(x2, nullptr, ln1_g, ln1_b, nullptr, hh, hl);               /* 2 */
    wsplit_qkv_k<<<(2*t1+255)/256, 256>>>(Wqk, Wv, wqvh, wqvl);                     /* 3 */
    blk_gemm_k<<<gQ, 512, PGSMEM>>>(hh, hl, wqvh, wqvl,                             /* 4 */
                                    1, 2*DDIM, nullptr, nullptr, qkv,
                                    nullptr, nullptr, 0);
    wsplit_k<<<(t1+255)/256, 256>>>(Wo,  woh,  wol,  DDIM, DDIM, 0, DDIM, t1);      /* 5 */
    wsplit_k<<<(t2+255)/256, 256>>>(W1,  w1h,  w1l,  DDIM, FFD,  0, FFD,  t2);      /* 6 */
    wsplit_k<<<(t2+255)/256, 256>>>(W2,  w2h,  w2l,  FFD,  DDIM, 0, DDIM, t2);      /* 7 */

    for (int d = 0; d < NDEPTH; d++) {
        size_t wsq = (size_t)d*DDIM*DDIM;
        if (d > 0) {
            ln_k<<<BLD/4, 128>>>(x2, nullptr, ln1_g + d*DDIM, ln1_b + d*DDIM,
                                 nullptr, hh, hl);
            blk_gemm_k<<<gQ, 512, PGSMEM>>>(hh, hl,
                                            wqvh + (size_t)d*2*DDIM*DDIM,
                                            wqvl + (size_t)d*2*DDIM*DDIM,
                                            1, 2*DDIM, nullptr, nullptr, qkv,
                                            nullptr, nullptr, 0);
        }
        attn_k<<<BB*HH, 384>>>(qkv, oh, ol);
        /* x1 = x1 + o@Wo + bo */
        blk_gemm_k<<<gD, 512, PGSMEM>>>(oh, ol, woh + wsq, wol + wsq,
                                        1, DDIM, bo + d*DDIM, x1, x1,
                                        nullptr, nullptr, 0);
        ln_k<<<BLD/4, 128>>>(x1, nullptr, ln2_g + d*DDIM, ln2_b + d*DDIM,
                             nullptr, hh, hl);
        /* a = gelu(h@W1 + b1) -> panelized split */
        blk_gemm_k<<<gF, 512, PGSMEM>>>(hh, hl,
                                        w1h + (size_t)d*DDIM*FFD, w1l + (size_t)d*DDIM*FFD,
                                        1, FFD, b1 + d*FFD, nullptr, nullptr,
                                        ah, al, 1);
        /* x2 = x2 + a@W2 + b2   (A = 4 panels, B = 4 panels) */
        blk_gemm_k<<<gD, 512, PGSMEM>>>(ah, al,
                                        w2h + (size_t)d*FFD*DDIM, w2l + (size_t)d*FFD*DDIM,
                                        4, DDIM, b2 + d*DDIM, x2, x2,
                                        nullptr, nullptr, 0);
    }

    ln_k<<<BLD/4, 128>>>(x1, x2, lnf_g, lnf_b, h, nullptr, nullptr);
    dim3 gp(8, NSPLIT);
    proj_partial_k<<<gp, 256>>>(h, Wp, part);
    proj_reduce_k<<<NSPLIT, 256>>>(part, bp, (float*)d_out);
}